// round 12
// baseline (speedup 1.0000x reference)
#include <cuda_runtime.h>
#include <cuda_bf16.h>
#include <math.h>
#include <stdint.h>

#define HIDDEN 4096
#define NHEADS 32
#define DK     128
#define BATCH  2
#define SEQ    2048
#define MTOK   (BATCH*SEQ)   // 4096

// GEMM tiling (mma.sync bf16): 64x128 CTA tile, 2-stage, 2 CTAs/SM
#define MT 64
#define NT 128
#define NCHUNK (HIDDEN / 64)   // 64
#define ST_A 8192              // 64 rows x 128B
#define ST_B 16384             // 128 rows x 128B
#define STAGE_BYTES (2*ST_A + 2*ST_B)   // 49152
#define SMEM_GEMM (2 * STAGE_BYTES)     // 98304 -> 2 CTAs/SM

// attention smem layout (bytes)
#define A_SQH 0
#define A_SQL 32768
#define A_SKH 65536
#define A_SKL 98304
#define A_SVH 131072
#define A_SVL 163840
#define SMEM_ATTN 196608

#define LOG2E 1.4426950408889634f
#define QSCALE 0.08838834764831845f   // 1/sqrt(128)

// ---------------- scratch ----------------------------------------------------
__device__ __nv_bfloat16 g_qh [MTOK * HIDDEN];
__device__ __nv_bfloat16 g_ql [MTOK * HIDDEN];
__device__ __nv_bfloat16 g_kh [MTOK * HIDDEN];
__device__ __nv_bfloat16 g_kl [MTOK * HIDDEN];
__device__ __nv_bfloat16 g_vh [MTOK * HIDDEN];
__device__ __nv_bfloat16 g_vl [MTOK * HIDDEN];
__device__ __nv_bfloat16 g_aoh[MTOK * HIDDEN];
__device__ __nv_bfloat16 g_aol[MTOK * HIDDEN];
__device__ __nv_bfloat16 g_xh [MTOK * HIDDEN];
__device__ __nv_bfloat16 g_xl [MTOK * HIDDEN];
__device__ __nv_bfloat16 g_wqh[HIDDEN * HIDDEN];
__device__ __nv_bfloat16 g_wql[HIDDEN * HIDDEN];
__device__ __nv_bfloat16 g_wkh[HIDDEN * HIDDEN];
__device__ __nv_bfloat16 g_wkl[HIDDEN * HIDDEN];
__device__ __nv_bfloat16 g_wvh[HIDDEN * HIDDEN];
__device__ __nv_bfloat16 g_wvl[HIDDEN * HIDDEN];
__device__ __nv_bfloat16 g_woh[HIDDEN * HIDDEN];
__device__ __nv_bfloat16 g_wol[HIDDEN * HIDDEN];

// ---------------- PTX helpers -------------------------------------------------
__device__ __forceinline__ uint32_t smem_u32(const void* p) {
    uint32_t a;
    asm("{ .reg .u64 t; cvta.to.shared.u64 t, %1; cvt.u32.u64 %0, t; }"
        : "=r"(a) : "l"(p));
    return a;
}
__device__ __forceinline__ void cp16(uint32_t dst, const void* src) {
    asm volatile("cp.async.cg.shared.global [%0], [%1], 16;"
                 :: "r"(dst), "l"(src) : "memory");
}
#define CP_COMMIT() asm volatile("cp.async.commit_group;" ::: "memory")
#define CP_WAIT(n)  asm volatile("cp.async.wait_group %0;" :: "n"(n) : "memory")

__device__ __forceinline__ void ldsm_x4(uint32_t& r0, uint32_t& r1,
                                        uint32_t& r2, uint32_t& r3, uint32_t a) {
    asm volatile("ldmatrix.sync.aligned.m8n8.x4.shared.b16 {%0,%1,%2,%3}, [%4];"
                 : "=r"(r0), "=r"(r1), "=r"(r2), "=r"(r3) : "r"(a));
}
__device__ __forceinline__ void ldsm_x4_t(uint32_t& r0, uint32_t& r1,
                                          uint32_t& r2, uint32_t& r3, uint32_t a) {
    asm volatile("ldmatrix.sync.aligned.m8n8.x4.trans.shared.b16 {%0,%1,%2,%3}, [%4];"
                 : "=r"(r0), "=r"(r1), "=r"(r2), "=r"(r3) : "r"(a));
}
__device__ __forceinline__ void mma_bf16(float* c, const uint32_t* a,
                                         uint32_t b0, uint32_t b1) {
    asm volatile(
        "mma.sync.aligned.m16n8k16.row.col.f32.bf16.bf16.f32 "
        "{%0,%1,%2,%3}, {%4,%5,%6,%7}, {%8,%9}, {%0,%1,%2,%3};"
        : "+f"(c[0]), "+f"(c[1]), "+f"(c[2]), "+f"(c[3])
        : "r"(a[0]), "r"(a[1]), "r"(a[2]), "r"(a[3]), "r"(b0), "r"(b1));
}
__device__ __forceinline__ uint32_t packbf2(__nv_bfloat16 a, __nv_bfloat16 b) {
    __nv_bfloat162 t = __halves2bfloat162(a, b);
    return *(uint32_t*)&t;
}
__device__ __forceinline__ void split2(float a, float b, uint32_t& hi, uint32_t& lo) {
    __nv_bfloat16 ha = __float2bfloat16(a), hb = __float2bfloat16(b);
    __nv_bfloat16 la = __float2bfloat16(a - __bfloat162float(ha));
    __nv_bfloat16 lb = __float2bfloat16(b - __bfloat162float(hb));
    hi = packbf2(ha, hb);
    lo = packbf2(la, lb);
}

// ---------------- fused fp32 -> bf16 hi/lo split (5 tensors, one launch) -------
__global__ __launch_bounds__(256)
void cvt_hilo5(const float4* __restrict__ s0, __nv_bfloat162* __restrict__ h0, __nv_bfloat162* __restrict__ l0,
               const float4* __restrict__ s1, __nv_bfloat162* __restrict__ h1, __nv_bfloat162* __restrict__ l1,
               const float4* __restrict__ s2, __nv_bfloat162* __restrict__ h2, __nv_bfloat162* __restrict__ l2,
               const float4* __restrict__ s3, __nv_bfloat162* __restrict__ h3, __nv_bfloat162* __restrict__ l3,
               const float4* __restrict__ s4, __nv_bfloat162* __restrict__ h4, __nv_bfloat162* __restrict__ l4)
{
    const int t = blockIdx.y;
    const float4* s = (t == 0) ? s0 : (t == 1) ? s1 : (t == 2) ? s2 : (t == 3) ? s3 : s4;
    __nv_bfloat162* h = (t == 0) ? h0 : (t == 1) ? h1 : (t == 2) ? h2 : (t == 3) ? h3 : h4;
    __nv_bfloat162* l = (t == 0) ? l0 : (t == 1) ? l1 : (t == 2) ? l2 : (t == 3) ? l3 : l4;

    size_t i = (size_t)blockIdx.x * 256 + threadIdx.x;
    float4 v = s[i];
    uint32_t a0, b0, a1, b1;
    split2(v.x, v.y, a0, b0);
    split2(v.z, v.w, a1, b1);
    ((uint32_t*)h)[2*i]   = a0;
    ((uint32_t*)h)[2*i+1] = a1;
    ((uint32_t*)l)[2*i]   = b0;
    ((uint32_t*)l)[2*i+1] = b1;
}

// ---------------- bf16 3-pass GEMM via mma.sync, 64x128 tile, 2 CTAs/SM --------
// C = (Ah+Al)[M,K] @ (Bh+Bl)[N,K]^T (drop Al*Bl).
__global__ __launch_bounds__(256, 2)
void gemm_mma_3p(const __nv_bfloat16* __restrict__ Ah,
                 const __nv_bfloat16* __restrict__ Al,
                 const __nv_bfloat16* __restrict__ Bh,
                 const __nv_bfloat16* __restrict__ Bl,
                 float* __restrict__ Cf,
                 __nv_bfloat16* __restrict__ Ch,
                 __nv_bfloat16* __restrict__ Cl,
                 float scale)
{
    extern __shared__ __align__(1024) char smem[];
    const uint32_t sb = smem_u32(smem);
    const int tid  = threadIdx.x;
    const int wid  = tid >> 5;
    const int lane = tid & 31;
    const int bm   = blockIdx.y * MT;
    const int bn   = blockIdx.x * NT;

    // warp grid: 2 (m) x 4 (n); warp tile 32x32
    const int wm0 = (wid & 1) * 32;
    const int wn0 = (wid >> 1) * 32;

    const char* gah = (const char*)Ah + (size_t)bm * (HIDDEN * 2);
    const char* gal = (const char*)Al + (size_t)bm * (HIDDEN * 2);
    const char* gbh = (const char*)Bh + (size_t)bn * (HIDDEN * 2);
    const char* gbl = (const char*)Bl + (size_t)bn * (HIDDEN * 2);

    const int a_r = lane & 15;
    const uint32_t a_k16 = (lane >> 4) * 16;
    uint32_t a_rb[2], a_xm[2];
    #pragma unroll
    for (int i = 0; i < 2; i++) {
        int row = wm0 + i * 16 + a_r;
        a_rb[i] = (uint32_t)row * 128;
        a_xm[i] = (uint32_t)(row & 7) * 16;
    }
    const int b_r = ((lane >> 4) & 1) * 8 + (lane & 7);
    const uint32_t b_k16 = ((lane >> 3) & 1) * 16;
    uint32_t b_rb[2], b_xm[2];
    #pragma unroll
    for (int j = 0; j < 2; j++) {
        int row = wn0 + j * 16 + b_r;
        b_rb[j] = (uint32_t)row * 128;
        b_xm[j] = (uint32_t)(row & 7) * 16;
    }

    float acc[2][4][4] = {};

    auto load_stage = [&](int s, int c) {
        const uint32_t st = sb + (uint32_t)s * STAGE_BYTES;
        const size_t cb = (size_t)c * 128;
        // A tiles: 512 units each -> 2 per thread
        #pragma unroll
        for (int u = 0; u < 2; u++) {
            int idx = u * 256 + tid;
            uint32_t bo = (uint32_t)idx << 4;
            uint32_t sw = bo ^ ((bo >> 3) & 0x70);
            size_t go = (size_t)(idx >> 3) * (HIDDEN * 2) + (size_t)(idx & 7) * 16 + cb;
            cp16(st + sw, gah + go);
            cp16(st + ST_A + sw, gal + go);
        }
        // B tiles: 1024 units each -> 4 per thread
        #pragma unroll
        for (int u = 0; u < 4; u++) {
            int idx = u * 256 + tid;
            uint32_t bo = (uint32_t)idx << 4;
            uint32_t sw = bo ^ ((bo >> 3) & 0x70);
            size_t go = (size_t)(idx >> 3) * (HIDDEN * 2) + (size_t)(idx & 7) * 16 + cb;
            cp16(st + 2 * ST_A + sw, gbh + go);
            cp16(st + 2 * ST_A + ST_B + sw, gbl + go);
        }
        CP_COMMIT();
    };

    load_stage(0, 0);

    for (int c = 0; c < NCHUNK; c++) {
        CP_WAIT(0);
        __syncthreads();
        if (c + 1 < NCHUNK) load_stage((c + 1) & 1, c + 1);

        const uint32_t st  = sb + (uint32_t)(c & 1) * STAGE_BYTES;
        const uint32_t tAh = st;
        const uint32_t tAl = st + ST_A;
        const uint32_t tBh = st + 2 * ST_A;
        const uint32_t tBl = st + 2 * ST_A + ST_B;

        #pragma unroll
        for (int ks = 0; ks < 4; ks++) {
            const uint32_t ak = (uint32_t)ks * 32 + a_k16;
            const uint32_t bk = (uint32_t)ks * 32 + b_k16;

            uint32_t ah[2][4], al[2][4], bh[2][4], bl[2][4];
            #pragma unroll
            for (int i = 0; i < 2; i++) {
                uint32_t off = a_rb[i] + (ak ^ a_xm[i]);
                ldsm_x4(ah[i][0], ah[i][1], ah[i][2], ah[i][3], tAh + off);
                ldsm_x4(al[i][0], al[i][1], al[i][2], al[i][3], tAl + off);
            }
            #pragma unroll
            for (int j = 0; j < 2; j++) {
                uint32_t off = b_rb[j] + (bk ^ b_xm[j]);
                ldsm_x4(bh[j][0], bh[j][1], bh[j][2], bh[j][3], tBh + off);
                ldsm_x4(bl[j][0], bl[j][1], bl[j][2], bl[j][3], tBl + off);
            }
            // pass 1: Ah*Bh over all 8 accumulators
            #pragma unroll
            for (int i = 0; i < 2; i++)
                #pragma unroll
                for (int j = 0; j < 4; j++)
                    mma_bf16(acc[i][j], ah[i],
                             bh[j >> 1][(j & 1) * 2], bh[j >> 1][(j & 1) * 2 + 1]);
            // pass 2: Ah*Bl
            #pragma unroll
            for (int i = 0; i < 2; i++)
                #pragma unroll
                for (int j = 0; j < 4; j++)
                    mma_bf16(acc[i][j], ah[i],
                             bl[j >> 1][(j & 1) * 2], bl[j >> 1][(j & 1) * 2 + 1]);
            // pass 3: Al*Bh
            #pragma unroll
            for (int i = 0; i < 2; i++)
                #pragma unroll
                for (int j = 0; j < 4; j++)
                    mma_bf16(acc[i][j], al[i],
                             bh[j >> 1][(j & 1) * 2], bh[j >> 1][(j & 1) * 2 + 1]);
        }
    }

    const int cr = lane >> 2;
    const int cc = (lane & 3) * 2;
    #pragma unroll
    for (int i = 0; i < 2; i++) {
        #pragma unroll
        for (int j = 0; j < 4; j++) {
            int row = bm + wm0 + i * 16 + cr;
            int col = bn + wn0 + j * 8 + cc;
            if (Cf) {
                *(float2*)(Cf + (size_t)row * HIDDEN + col) =
                    make_float2(acc[i][j][0], acc[i][j][1]);
                *(float2*)(Cf + (size_t)(row + 8) * HIDDEN + col) =
                    make_float2(acc[i][j][2], acc[i][j][3]);
            } else {
                uint32_t h0, l0, h1, l1;
                split2(acc[i][j][0] * scale, acc[i][j][1] * scale, h0, l0);
                split2(acc[i][j][2] * scale, acc[i][j][3] * scale, h1, l1);
                *(uint32_t*)(Ch + (size_t)row * HIDDEN + col)       = h0;
                *(uint32_t*)(Cl + (size_t)row * HIDDEN + col)       = l0;
                *(uint32_t*)(Ch + (size_t)(row + 8) * HIDDEN + col) = h1;
                *(uint32_t*)(Cl + (size_t)(row + 8) * HIDDEN + col) = l1;
            }
        }
    }
}

// ---------------- flash attention via mma.sync (split bf16, 3-pass) ------------
__global__ __launch_bounds__(256)
void attn_mma(const __nv_bfloat16* __restrict__ Qh, const __nv_bfloat16* __restrict__ Ql,
              const __nv_bfloat16* __restrict__ Kh, const __nv_bfloat16* __restrict__ Kl,
              const __nv_bfloat16* __restrict__ Vh, const __nv_bfloat16* __restrict__ Vl,
              __nv_bfloat16* __restrict__ AOh, __nv_bfloat16* __restrict__ AOl)
{
    extern __shared__ __align__(1024) char smem[];
    const uint32_t sb = smem_u32(smem);
    const int tid  = threadIdx.x;
    const int wid  = tid >> 5;
    const int lane = tid & 31;
    const int q0   = blockIdx.x * 128;
    const int h    = blockIdx.y;
    const int b    = blockIdx.z;

    const size_t hb = ((size_t)b * SEQ) * HIDDEN + (size_t)h * DK;
    const char* gqh = (const char*)(Qh + hb + (size_t)q0 * HIDDEN);
    const char* gql = (const char*)(Ql + hb + (size_t)q0 * HIDDEN);
    const char* gkh = (const char*)(Kh + hb);
    const char* gkl = (const char*)(Kl + hb);
    const char* gvh = (const char*)(Vh + hb);
    const char* gvl = (const char*)(Vl + hb);

    auto load_tile = [&](uint32_t soff, const char* g) {
        #pragma unroll
        for (int r = 0; r < 8; r++) {
            int idx = r * 256 + tid;
            int row = idx >> 4, u = idx & 15;
            uint32_t sa = sb + soff + (uint32_t)(u >> 3) * 16384
                        + (uint32_t)row * 128
                        + (((uint32_t)(u & 7) * 16) ^ ((uint32_t)(row & 7) * 16));
            cp16(sa, g + (size_t)row * (HIDDEN * 2) + (size_t)u * 16);
        }
    };

    load_tile(A_SQH, gqh);
    load_tile(A_SQL, gql);
    load_tile(A_SKH, gkh);
    load_tile(A_SKL, gkl);
    CP_COMMIT();
    CP_WAIT(0);
    __syncthreads();

    float of[16][4] = {};
    float m0 = -INFINITY, m1 = -INFINITY, l0 = 0.f, l1 = 0.f;

    const uint32_t q_row = (uint32_t)(16 * wid + (lane & 15));
    const uint32_t q_kof = (uint32_t)(lane >> 4) * 16;
    const uint32_t q_xm  = (q_row & 7) * 16;
    const uint32_t q_rb  = q_row * 128;

    const uint32_t k_r   = (uint32_t)(((lane >> 4) & 1) * 8 + (lane & 7));
    const uint32_t k_kof = (uint32_t)((lane >> 3) & 1) * 16;

    const int v_grp  = lane >> 3;
    const uint32_t v_krow = (uint32_t)((v_grp & 1) * 8 + (lane & 7));
    const uint32_t v_ncol = (uint32_t)((v_grp >> 1) * 8);

    for (int t = 0; t < 16; t++) {
        load_tile(A_SVH, gvh + (size_t)t * 128 * (HIDDEN * 2));
        load_tile(A_SVL, gvl + (size_t)t * 128 * (HIDDEN * 2));
        CP_COMMIT();

        float sf[16][4] = {};
        #pragma unroll
        for (int ks = 0; ks < 8; ks++) {
            uint32_t qa = sb + A_SQH + (uint32_t)(ks >> 2) * 16384 + q_rb
                        + ((((uint32_t)(ks & 3) * 32) + q_kof) ^ q_xm);
            uint32_t qh4[4], ql4[4];
            ldsm_x4(qh4[0], qh4[1], qh4[2], qh4[3], qa);
            ldsm_x4(ql4[0], ql4[1], ql4[2], ql4[3], qa + (A_SQL - A_SQH));
            #pragma unroll
            for (int j16 = 0; j16 < 8; j16++) {
                uint32_t krow = (uint32_t)j16 * 16 + k_r;
                uint32_t ka = sb + A_SKH + (uint32_t)(ks >> 2) * 16384 + krow * 128
                            + ((((uint32_t)(ks & 3) * 32) + k_kof) ^ ((krow & 7) * 16));
                uint32_t kh4[4], kl4[4];
                ldsm_x4(kh4[0], kh4[1], kh4[2], kh4[3], ka);
                ldsm_x4(kl4[0], kl4[1], kl4[2], kl4[3], ka + (A_SKL - A_SKH));
                mma_bf16(sf[2*j16],   qh4, kh4[0], kh4[1]);
                mma_bf16(sf[2*j16+1], qh4, kh4[2], kh4[3]);
                mma_bf16(sf[2*j16],   qh4, kl4[0], kl4[1]);
                mma_bf16(sf[2*j16+1], qh4, kl4[2], kl4[3]);
                mma_bf16(sf[2*j16],   ql4, kh4[0], kh4[1]);
                mma_bf16(sf[2*j16+1], ql4, kh4[2], kh4[3]);
            }
        }

        CP_WAIT(0);
        __syncthreads();

        if (t + 1 < 16) {
            load_tile(A_SKH, gkh + (size_t)(t + 1) * 128 * (HIDDEN * 2));
            load_tile(A_SKL, gkl + (size_t)(t + 1) * 128 * (HIDDEN * 2));
            CP_COMMIT();
        }

        float tm0 = m0, tm1 = m1;
        #pragma unroll
        for (int f = 0; f < 16; f++) {
            tm0 = fmaxf(tm0, fmaxf(sf[f][0], sf[f][1]));
            tm1 = fmaxf(tm1, fmaxf(sf[f][2], sf[f][3]));
        }
        tm0 = fmaxf(tm0, __shfl_xor_sync(0xffffffff, tm0, 1));
        tm0 = fmaxf(tm0, __shfl_xor_sync(0xffffffff, tm0, 2));
        tm1 = fmaxf(tm1, __shfl_xor_sync(0xffffffff, tm1, 1));
        tm1 = fmaxf(tm1, __shfl_xor_sync(0xffffffff, tm1, 2));
        float cor0 = exp2f((m0 - tm0) * LOG2E);
        float cor1 = exp2f((m1 - tm1) * LOG2E);
        m0 = tm0; m1 = tm1;
        float s0 = 0.f, s1 = 0.f;
        #pragma unroll
        for (int f = 0; f < 16; f++) {
            sf[f][0] = exp2f((sf[f][0] - m0) * LOG2E);
            sf[f][1] = exp2f((sf[f][1] - m0) * LOG2E);
            sf[f][2] = exp2f((sf[f][2] - m1) * LOG2E);
            sf[f][3] = exp2f((sf[f][3] - m1) * LOG2E);
            s0 += sf[f][0] + sf[f][1];
            s1 += sf[f][2] + sf[f][3];
        }
        s0 += __shfl_xor_sync(0xffffffff, s0, 1);
        s0 += __shfl_xor_sync(0xffffffff, s0, 2);
        s1 += __shfl_xor_sync(0xffffffff, s1, 1);
        s1 += __shfl_xor_sync(0xffffffff, s1, 2);
        l0 = l0 * cor0 + s0;
        l1 = l1 * cor1 + s1;
        #pragma unroll
        for (int f = 0; f < 16; f++) {
            of[f][0] *= cor0; of[f][1] *= cor0;
            of[f][2] *= cor1; of[f][3] *= cor1;
        }

        #pragma unroll
        for (int ks = 0; ks < 8; ks++) {
            uint32_t pah[4], pal[4];
            split2(sf[2*ks][0],   sf[2*ks][1],   pah[0], pal[0]);
            split2(sf[2*ks][2],   sf[2*ks][3],   pah[1], pal[1]);
            split2(sf[2*ks+1][0], sf[2*ks+1][1], pah[2], pal[2]);
            split2(sf[2*ks+1][2], sf[2*ks+1][3], pah[3], pal[3]);
            uint32_t vkey = (uint32_t)ks * 16 + v_krow;
            #pragma unroll
            for (int j16 = 0; j16 < 8; j16++) {
                uint32_t ncol = (uint32_t)j16 * 16 + v_ncol;
                uint32_t va = sb + A_SVH + (ncol >> 6) * 16384 + vkey * 128
                            + (((ncol & 63) * 2) ^ ((vkey & 7) * 16));
                uint32_t vh4[4], vl4[4];
                ldsm_x4_t(vh4[0], vh4[1], vh4[2], vh4[3], va);
                ldsm_x4_t(vl4[0], vl4[1], vl4[2], vl4[3], va + (A_SVL - A_SVH));
                mma_bf16(of[2*j16],   pah, vh4[0], vh4[1]);
                mma_bf16(of[2*j16+1], pah, vh4[2], vh4[3]);
                mma_bf16(of[2*j16],   pah, vl4[0], vl4[1]);
                mma_bf16(of[2*j16+1], pah, vl4[2], vl4[3]);
                mma_bf16(of[2*j16],   pal, vh4[0], vh4[1]);
                mma_bf16(of[2*j16+1], pal, vh4[2], vh4[3]);
            }
        }

        CP_WAIT(0);
        __syncthreads();
    }

    const float inv0 = 1.f / l0;
    const float inv1 = 1.f / l1;
    const int r0 = q0 + 16 * wid + (lane >> 2);
    const int cc = (lane & 3) * 2;
    #pragma unroll
    for (int f = 0; f < 16; f++) {
        int col = f * 8 + cc;
        uint32_t h0, lo0, h1, lo1;
        split2(of[f][0] * inv0, of[f][1] * inv0, h0, lo0);
        split2(of[f][2] * inv1, of[f][3] * inv1, h1, lo1);
        size_t o0 = hb + (size_t)r0 * HIDDEN + col;
        size_t o1 = hb + (size_t)(r0 + 8) * HIDDEN + col;
        *(uint32_t*)(AOh + o0) = h0;
        *(uint32_t*)(AOl + o0) = lo0;
        *(uint32_t*)(AOh + o1) = h1;
        *(uint32_t*)(AOl + o1) = lo1;
    }
}

// ------------------------------------------------------------------------------
extern "C" void kernel_launch(void* const* d_in, const int* in_sizes, int n_in,
                              void* d_out, int out_size)
{
    const float* x  = (const float*)d_in[0];
    const float* wq = (const float*)d_in[1];
    const float* wk = (const float*)d_in[2];
    const float* wv = (const float*)d_in[3];
    const float* wo = (const float*)d_in[4];
    float* out = (float*)d_out;

    __nv_bfloat16 *qh, *ql, *kh, *kl, *vh, *vl, *aoh, *aol, *xh, *xl;
    __nv_bfloat16 *wqh, *wql, *wkh, *wkl, *wvh, *wvl, *woh, *wol;
    cudaGetSymbolAddress((void**)&qh,  g_qh);  cudaGetSymbolAddress((void**)&ql,  g_ql);
    cudaGetSymbolAddress((void**)&kh,  g_kh);  cudaGetSymbolAddress((void**)&kl,  g_kl);
    cudaGetSymbolAddress((void**)&vh,  g_vh);  cudaGetSymbolAddress((void**)&vl,  g_vl);
    cudaGetSymbolAddress((void**)&aoh, g_aoh); cudaGetSymbolAddress((void**)&aol, g_aol);
    cudaGetSymbolAddress((void**)&xh,  g_xh);  cudaGetSymbolAddress((void**)&xl,  g_xl);
    cudaGetSymbolAddress((void**)&wqh, g_wqh); cudaGetSymbolAddress((void**)&wql, g_wql);
    cudaGetSymbolAddress((void**)&wkh, g_wkh); cudaGetSymbolAddress((void**)&wkl, g_wkl);
    cudaGetSymbolAddress((void**)&wvh, g_wvh); cudaGetSymbolAddress((void**)&wvl, g_wvl);
    cudaGetSymbolAddress((void**)&woh, g_woh); cudaGetSymbolAddress((void**)&wol, g_wol);

    cudaFuncSetAttribute(gemm_mma_3p, cudaFuncAttributeMaxDynamicSharedMemorySize,
                         SMEM_GEMM);
    cudaFuncSetAttribute(attn_mma, cudaFuncAttributeMaxDynamicSharedMemorySize,
                         SMEM_ATTN);

    // one fused convert launch for all 5 input tensors
    dim3 gcvt((HIDDEN * HIDDEN) / 4 / 256, 5);   // (16384, 5)
    cvt_hilo5<<<gcvt, 256>>>(
        (const float4*)x,  (__nv_bfloat162*)xh,  (__nv_bfloat162*)xl,
        (const float4*)wq, (__nv_bfloat162*)wqh, (__nv_bfloat162*)wql,
        (const float4*)wk, (__nv_bfloat162*)wkh, (__nv_bfloat162*)wkl,
        (const float4*)wv, (__nv_bfloat162*)wvh, (__nv_bfloat162*)wvl,
        (const float4*)wo, (__nv_bfloat162*)woh, (__nv_bfloat162*)wol);

    dim3 gg(HIDDEN / NT, MTOK / MT);   // (32, 64) = 2048 CTAs
    gemm_mma_3p<<<gg, 256, SMEM_GEMM>>>(xh, xl, wqh, wql, nullptr, qh, ql, QSCALE);
    gemm_mma_3p<<<gg, 256, SMEM_GEMM>>>(xh, xl, wkh, wkl, nullptr, kh, kl, 1.0f);
    gemm_mma_3p<<<gg, 256, SMEM_GEMM>>>(xh, xl, wvh, wvl, nullptr, vh, vl, 1.0f);

    dim3 ga(SEQ / 128, NHEADS, BATCH); // (16, 32, 2)
    attn_mma<<<ga, 256, SMEM_ATTN>>>(qh, ql, kh, kl, vh, vl, aoh, aol);

    gemm_mma_3p<<<gg, 256, SMEM_GEMM>>>(aoh, aol, woh, wol, out, nullptr, nullptr, 1.0f);
}

// round 13
// speedup vs baseline: 1.0007x; 1.0007x over previous
#include <cuda_runtime.h>
#include <cuda_bf16.h>
#include <math.h>
#include <stdint.h>

#define HIDDEN 4096
#define NHEADS 32
#define DK     128
#define BATCH  2
#define SEQ    2048
#define MTOK   (BATCH*SEQ)   // 4096

// GEMM tiling (mma.sync bf16): 64x128 CTA tile, 2-stage, 2 CTAs/SM
#define MT 64
#define NT 128
#define NCHUNK (HIDDEN / 64)   // 64
#define ST_A 8192              // 64 rows x 128B
#define ST_B 16384             // 128 rows x 128B
#define STAGE_BYTES (2*ST_A + 2*ST_B)   // 49152
#define SMEM_GEMM (2 * STAGE_BYTES)     // 98304 -> 2 CTAs/SM

// attention smem layout (bytes)
#define A_SQH 0
#define A_SQL 32768
#define A_SKH 65536
#define A_SKL 98304
#define A_SVH 131072
#define A_SVL 163840
#define SMEM_ATTN 196608

#define LOG2E 1.4426950408889634f
#define QSCALE 0.08838834764831845f   // 1/sqrt(128)

// ---------------- scratch ----------------------------------------------------
__device__ __nv_bfloat16 g_qh [MTOK * HIDDEN];
__device__ __nv_bfloat16 g_ql [MTOK * HIDDEN];
__device__ __nv_bfloat16 g_kh [MTOK * HIDDEN];
__device__ __nv_bfloat16 g_kl [MTOK * HIDDEN];
__device__ __nv_bfloat16 g_vh [MTOK * HIDDEN];
__device__ __nv_bfloat16 g_vl [MTOK * HIDDEN];
__device__ __nv_bfloat16 g_aoh[MTOK * HIDDEN];
__device__ __nv_bfloat16 g_aol[MTOK * HIDDEN];
__device__ __nv_bfloat16 g_xh [MTOK * HIDDEN];
__device__ __nv_bfloat16 g_xl [MTOK * HIDDEN];
__device__ __nv_bfloat16 g_wqh[HIDDEN * HIDDEN];
__device__ __nv_bfloat16 g_wql[HIDDEN * HIDDEN];
__device__ __nv_bfloat16 g_wkh[HIDDEN * HIDDEN];
__device__ __nv_bfloat16 g_wkl[HIDDEN * HIDDEN];
__device__ __nv_bfloat16 g_wvh[HIDDEN * HIDDEN];
__device__ __nv_bfloat16 g_wvl[HIDDEN * HIDDEN];
__device__ __nv_bfloat16 g_woh[HIDDEN * HIDDEN];
__device__ __nv_bfloat16 g_wol[HIDDEN * HIDDEN];

// ---------------- PTX helpers -------------------------------------------------
__device__ __forceinline__ uint32_t smem_u32(const void* p) {
    uint32_t a;
    asm("{ .reg .u64 t; cvta.to.shared.u64 t, %1; cvt.u32.u64 %0, t; }"
        : "=r"(a) : "l"(p));
    return a;
}
__device__ __forceinline__ void cp16(uint32_t dst, const void* src) {
    asm volatile("cp.async.cg.shared.global [%0], [%1], 16;"
                 :: "r"(dst), "l"(src) : "memory");
}
#define CP_COMMIT() asm volatile("cp.async.commit_group;" ::: "memory")
#define CP_WAIT(n)  asm volatile("cp.async.wait_group %0;" :: "n"(n) : "memory")

__device__ __forceinline__ void ldsm_x4(uint32_t& r0, uint32_t& r1,
                                        uint32_t& r2, uint32_t& r3, uint32_t a) {
    asm volatile("ldmatrix.sync.aligned.m8n8.x4.shared.b16 {%0,%1,%2,%3}, [%4];"
                 : "=r"(r0), "=r"(r1), "=r"(r2), "=r"(r3) : "r"(a));
}
__device__ __forceinline__ void ldsm_x4_t(uint32_t& r0, uint32_t& r1,
                                          uint32_t& r2, uint32_t& r3, uint32_t a) {
    asm volatile("ldmatrix.sync.aligned.m8n8.x4.trans.shared.b16 {%0,%1,%2,%3}, [%4];"
                 : "=r"(r0), "=r"(r1), "=r"(r2), "=r"(r3) : "r"(a));
}
__device__ __forceinline__ void mma_bf16(float* c, const uint32_t* a,
                                         uint32_t b0, uint32_t b1) {
    asm volatile(
        "mma.sync.aligned.m16n8k16.row.col.f32.bf16.bf16.f32 "
        "{%0,%1,%2,%3}, {%4,%5,%6,%7}, {%8,%9}, {%0,%1,%2,%3};"
        : "+f"(c[0]), "+f"(c[1]), "+f"(c[2]), "+f"(c[3])
        : "r"(a[0]), "r"(a[1]), "r"(a[2]), "r"(a[3]), "r"(b0), "r"(b1));
}
__device__ __forceinline__ uint32_t packbf2(__nv_bfloat16 a, __nv_bfloat16 b) {
    __nv_bfloat162 t = __halves2bfloat162(a, b);
    return *(uint32_t*)&t;
}
__device__ __forceinline__ void split2(float a, float b, uint32_t& hi, uint32_t& lo) {
    __nv_bfloat16 ha = __float2bfloat16(a), hb = __float2bfloat16(b);
    __nv_bfloat16 la = __float2bfloat16(a - __bfloat162float(ha));
    __nv_bfloat16 lb = __float2bfloat16(b - __bfloat162float(hb));
    hi = packbf2(ha, hb);
    lo = packbf2(la, lb);
}

// ---------------- fused fp32 -> bf16 hi/lo split (5 tensors, one launch) -------
__global__ __launch_bounds__(256)
void cvt_hilo5(const float4* __restrict__ s0, __nv_bfloat162* __restrict__ h0, __nv_bfloat162* __restrict__ l0,
               const float4* __restrict__ s1, __nv_bfloat162* __restrict__ h1, __nv_bfloat162* __restrict__ l1,
               const float4* __restrict__ s2, __nv_bfloat162* __restrict__ h2, __nv_bfloat162* __restrict__ l2,
               const float4* __restrict__ s3, __nv_bfloat162* __restrict__ h3, __nv_bfloat162* __restrict__ l3,
               const float4* __restrict__ s4, __nv_bfloat162* __restrict__ h4, __nv_bfloat162* __restrict__ l4)
{
    const int t = blockIdx.y;
    const float4* s = (t == 0) ? s0 : (t == 1) ? s1 : (t == 2) ? s2 : (t == 3) ? s3 : s4;
    __nv_bfloat162* h = (t == 0) ? h0 : (t == 1) ? h1 : (t == 2) ? h2 : (t == 3) ? h3 : h4;
    __nv_bfloat162* l = (t == 0) ? l0 : (t == 1) ? l1 : (t == 2) ? l2 : (t == 3) ? l3 : l4;

    size_t i = (size_t)blockIdx.x * 256 + threadIdx.x;
    float4 v = s[i];
    uint32_t a0, b0, a1, b1;
    split2(v.x, v.y, a0, b0);
    split2(v.z, v.w, a1, b1);
    ((uint32_t*)h)[2*i]   = a0;
    ((uint32_t*)h)[2*i+1] = a1;
    ((uint32_t*)l)[2*i]   = b0;
    ((uint32_t*)l)[2*i+1] = b1;
}

// ---------------- bf16 3-pass GEMM via mma.sync, 64x128 tile, 2 CTAs/SM --------
// C = (Ah+Al)[M,K] @ (Bh+Bl)[N,K]^T (drop Al*Bl).
__global__ __launch_bounds__(256, 2)
void gemm_mma_3p(const __nv_bfloat16* __restrict__ Ah,
                 const __nv_bfloat16* __restrict__ Al,
                 const __nv_bfloat16* __restrict__ Bh,
                 const __nv_bfloat16* __restrict__ Bl,
                 float* __restrict__ Cf,
                 __nv_bfloat16* __restrict__ Ch,
                 __nv_bfloat16* __restrict__ Cl,
                 float scale)
{
    extern __shared__ __align__(1024) char smem[];
    const uint32_t sb = smem_u32(smem);
    const int tid  = threadIdx.x;
    const int wid  = tid >> 5;
    const int lane = tid & 31;
    const int bm   = blockIdx.y * MT;
    const int bn   = blockIdx.x * NT;

    // warp grid: 2 (m) x 4 (n); warp tile 32x32
    const int wm0 = (wid & 1) * 32;
    const int wn0 = (wid >> 1) * 32;

    const char* gah = (const char*)Ah + (size_t)bm * (HIDDEN * 2);
    const char* gal = (const char*)Al + (size_t)bm * (HIDDEN * 2);
    const char* gbh = (const char*)Bh + (size_t)bn * (HIDDEN * 2);
    const char* gbl = (const char*)Bl + (size_t)bn * (HIDDEN * 2);

    const int a_r = lane & 15;
    const uint32_t a_k16 = (lane >> 4) * 16;
    uint32_t a_rb[2], a_xm[2];
    #pragma unroll
    for (int i = 0; i < 2; i++) {
        int row = wm0 + i * 16 + a_r;
        a_rb[i] = (uint32_t)row * 128;
        a_xm[i] = (uint32_t)(row & 7) * 16;
    }
    const int b_r = ((lane >> 4) & 1) * 8 + (lane & 7);
    const uint32_t b_k16 = ((lane >> 3) & 1) * 16;
    uint32_t b_rb[2], b_xm[2];
    #pragma unroll
    for (int j = 0; j < 2; j++) {
        int row = wn0 + j * 16 + b_r;
        b_rb[j] = (uint32_t)row * 128;
        b_xm[j] = (uint32_t)(row & 7) * 16;
    }

    float acc[2][4][4] = {};

    auto load_stage = [&](int s, int c) {
        const uint32_t st = sb + (uint32_t)s * STAGE_BYTES;
        const size_t cb = (size_t)c * 128;
        // A tiles: 512 units each -> 2 per thread
        #pragma unroll
        for (int u = 0; u < 2; u++) {
            int idx = u * 256 + tid;
            uint32_t bo = (uint32_t)idx << 4;
            uint32_t sw = bo ^ ((bo >> 3) & 0x70);
            size_t go = (size_t)(idx >> 3) * (HIDDEN * 2) + (size_t)(idx & 7) * 16 + cb;
            cp16(st + sw, gah + go);
            cp16(st + ST_A + sw, gal + go);
        }
        // B tiles: 1024 units each -> 4 per thread
        #pragma unroll
        for (int u = 0; u < 4; u++) {
            int idx = u * 256 + tid;
            uint32_t bo = (uint32_t)idx << 4;
            uint32_t sw = bo ^ ((bo >> 3) & 0x70);
            size_t go = (size_t)(idx >> 3) * (HIDDEN * 2) + (size_t)(idx & 7) * 16 + cb;
            cp16(st + 2 * ST_A + sw, gbh + go);
            cp16(st + 2 * ST_A + ST_B + sw, gbl + go);
        }
        CP_COMMIT();
    };

    load_stage(0, 0);

    for (int c = 0; c < NCHUNK; c++) {
        CP_WAIT(0);
        __syncthreads();
        if (c + 1 < NCHUNK) load_stage((c + 1) & 1, c + 1);

        const uint32_t st  = sb + (uint32_t)(c & 1) * STAGE_BYTES;
        const uint32_t tAh = st;
        const uint32_t tAl = st + ST_A;
        const uint32_t tBh = st + 2 * ST_A;
        const uint32_t tBl = st + 2 * ST_A + ST_B;

        #pragma unroll
        for (int ks = 0; ks < 4; ks++) {
            const uint32_t ak = (uint32_t)ks * 32 + a_k16;
            const uint32_t bk = (uint32_t)ks * 32 + b_k16;

            uint32_t ah[2][4], al[2][4], bh[2][4], bl[2][4];
            #pragma unroll
            for (int i = 0; i < 2; i++) {
                uint32_t off = a_rb[i] + (ak ^ a_xm[i]);
                ldsm_x4(ah[i][0], ah[i][1], ah[i][2], ah[i][3], tAh + off);
                ldsm_x4(al[i][0], al[i][1], al[i][2], al[i][3], tAl + off);
            }
            #pragma unroll
            for (int j = 0; j < 2; j++) {
                uint32_t off = b_rb[j] + (bk ^ b_xm[j]);
                ldsm_x4(bh[j][0], bh[j][1], bh[j][2], bh[j][3], tBh + off);
                ldsm_x4(bl[j][0], bl[j][1], bl[j][2], bl[j][3], tBl + off);
            }
            // pass 1: Ah*Bh over all 8 accumulators
            #pragma unroll
            for (int i = 0; i < 2; i++)
                #pragma unroll
                for (int j = 0; j < 4; j++)
                    mma_bf16(acc[i][j], ah[i],
                             bh[j >> 1][(j & 1) * 2], bh[j >> 1][(j & 1) * 2 + 1]);
            // pass 2: Ah*Bl
            #pragma unroll
            for (int i = 0; i < 2; i++)
                #pragma unroll
                for (int j = 0; j < 4; j++)
                    mma_bf16(acc[i][j], ah[i],
                             bl[j >> 1][(j & 1) * 2], bl[j >> 1][(j & 1) * 2 + 1]);
            // pass 3: Al*Bh
            #pragma unroll
            for (int i = 0; i < 2; i++)
                #pragma unroll
                for (int j = 0; j < 4; j++)
                    mma_bf16(acc[i][j], al[i],
                             bh[j >> 1][(j & 1) * 2], bh[j >> 1][(j & 1) * 2 + 1]);
        }
    }

    const int cr = lane >> 2;
    const int cc = (lane & 3) * 2;
    #pragma unroll
    for (int i = 0; i < 2; i++) {
        #pragma unroll
        for (int j = 0; j < 4; j++) {
            int row = bm + wm0 + i * 16 + cr;
            int col = bn + wn0 + j * 8 + cc;
            if (Cf) {
                *(float2*)(Cf + (size_t)row * HIDDEN + col) =
                    make_float2(acc[i][j][0], acc[i][j][1]);
                *(float2*)(Cf + (size_t)(row + 8) * HIDDEN + col) =
                    make_float2(acc[i][j][2], acc[i][j][3]);
            } else {
                uint32_t h0, l0, h1, l1;
                split2(acc[i][j][0] * scale, acc[i][j][1] * scale, h0, l0);
                split2(acc[i][j][2] * scale, acc[i][j][3] * scale, h1, l1);
                *(uint32_t*)(Ch + (size_t)row * HIDDEN + col)       = h0;
                *(uint32_t*)(Cl + (size_t)row * HIDDEN + col)       = l0;
                *(uint32_t*)(Ch + (size_t)(row + 8) * HIDDEN + col) = h1;
                *(uint32_t*)(Cl + (size_t)(row + 8) * HIDDEN + col) = l1;
            }
        }
    }
}

// ---------------- flash attention via mma.sync (split bf16, 3-pass) ------------
__global__ __launch_bounds__(256)
void attn_mma(const __nv_bfloat16* __restrict__ Qh, const __nv_bfloat16* __restrict__ Ql,
              const __nv_bfloat16* __restrict__ Kh, const __nv_bfloat16* __restrict__ Kl,
              const __nv_bfloat16* __restrict__ Vh, const __nv_bfloat16* __restrict__ Vl,
              __nv_bfloat16* __restrict__ AOh, __nv_bfloat16* __restrict__ AOl)
{
    extern __shared__ __align__(1024) char smem[];
    const uint32_t sb = smem_u32(smem);
    const int tid  = threadIdx.x;
    const int wid  = tid >> 5;
    const int lane = tid & 31;
    const int q0   = blockIdx.x * 128;
    const int h    = blockIdx.y;
    const int b    = blockIdx.z;

    const size_t hb = ((size_t)b * SEQ) * HIDDEN + (size_t)h * DK;
    const char* gqh = (const char*)(Qh + hb + (size_t)q0 * HIDDEN);
    const char* gql = (const char*)(Ql + hb + (size_t)q0 * HIDDEN);
    const char* gkh = (const char*)(Kh + hb);
    const char* gkl = (const char*)(Kl + hb);
    const char* gvh = (const char*)(Vh + hb);
    const char* gvl = (const char*)(Vl + hb);

    auto load_tile = [&](uint32_t soff, const char* g) {
        #pragma unroll
        for (int r = 0; r < 8; r++) {
            int idx = r * 256 + tid;
            int row = idx >> 4, u = idx & 15;
            uint32_t sa = sb + soff + (uint32_t)(u >> 3) * 16384
                        + (uint32_t)row * 128
                        + (((uint32_t)(u & 7) * 16) ^ ((uint32_t)(row & 7) * 16));
            cp16(sa, g + (size_t)row * (HIDDEN * 2) + (size_t)u * 16);
        }
    };

    load_tile(A_SQH, gqh);
    load_tile(A_SQL, gql);
    load_tile(A_SKH, gkh);
    load_tile(A_SKL, gkl);
    CP_COMMIT();
    CP_WAIT(0);
    __syncthreads();

    float of[16][4] = {};
    float m0 = -INFINITY, m1 = -INFINITY, l0 = 0.f, l1 = 0.f;

    const uint32_t q_row = (uint32_t)(16 * wid + (lane & 15));
    const uint32_t q_kof = (uint32_t)(lane >> 4) * 16;
    const uint32_t q_xm  = (q_row & 7) * 16;
    const uint32_t q_rb  = q_row * 128;

    const uint32_t k_r   = (uint32_t)(((lane >> 4) & 1) * 8 + (lane & 7));
    const uint32_t k_kof = (uint32_t)((lane >> 3) & 1) * 16;

    const int v_grp  = lane >> 3;
    const uint32_t v_krow = (uint32_t)((v_grp & 1) * 8 + (lane & 7));
    const uint32_t v_ncol = (uint32_t)((v_grp >> 1) * 8);

    for (int t = 0; t < 16; t++) {
        load_tile(A_SVH, gvh + (size_t)t * 128 * (HIDDEN * 2));
        load_tile(A_SVL, gvl + (size_t)t * 128 * (HIDDEN * 2));
        CP_COMMIT();

        float sf[16][4] = {};
        #pragma unroll
        for (int ks = 0; ks < 8; ks++) {
            uint32_t qa = sb + A_SQH + (uint32_t)(ks >> 2) * 16384 + q_rb
                        + ((((uint32_t)(ks & 3) * 32) + q_kof) ^ q_xm);
            uint32_t qh4[4], ql4[4];
            ldsm_x4(qh4[0], qh4[1], qh4[2], qh4[3], qa);
            ldsm_x4(ql4[0], ql4[1], ql4[2], ql4[3], qa + (A_SQL - A_SQH));
            #pragma unroll
            for (int j16 = 0; j16 < 8; j16++) {
                uint32_t krow = (uint32_t)j16 * 16 + k_r;
                uint32_t ka = sb + A_SKH + (uint32_t)(ks >> 2) * 16384 + krow * 128
                            + ((((uint32_t)(ks & 3) * 32) + k_kof) ^ ((krow & 7) * 16));
                uint32_t kh4[4], kl4[4];
                ldsm_x4(kh4[0], kh4[1], kh4[2], kh4[3], ka);
                ldsm_x4(kl4[0], kl4[1], kl4[2], kl4[3], ka + (A_SKL - A_SKH));
                mma_bf16(sf[2*j16],   qh4, kh4[0], kh4[1]);
                mma_bf16(sf[2*j16+1], qh4, kh4[2], kh4[3]);
                mma_bf16(sf[2*j16],   qh4, kl4[0], kl4[1]);
                mma_bf16(sf[2*j16+1], qh4, kl4[2], kl4[3]);
                mma_bf16(sf[2*j16],   ql4, kh4[0], kh4[1]);
                mma_bf16(sf[2*j16+1], ql4, kh4[2], kh4[3]);
            }
        }

        CP_WAIT(0);
        __syncthreads();

        if (t + 1 < 16) {
            load_tile(A_SKH, gkh + (size_t)(t + 1) * 128 * (HIDDEN * 2));
            load_tile(A_SKL, gkl + (size_t)(t + 1) * 128 * (HIDDEN * 2));
            CP_COMMIT();
        }

        float tm0 = m0, tm1 = m1;
        #pragma unroll
        for (int f = 0; f < 16; f++) {
            tm0 = fmaxf(tm0, fmaxf(sf[f][0], sf[f][1]));
            tm1 = fmaxf(tm1, fmaxf(sf[f][2], sf[f][3]));
        }
        tm0 = fmaxf(tm0, __shfl_xor_sync(0xffffffff, tm0, 1));
        tm0 = fmaxf(tm0, __shfl_xor_sync(0xffffffff, tm0, 2));
        tm1 = fmaxf(tm1, __shfl_xor_sync(0xffffffff, tm1, 1));
        tm1 = fmaxf(tm1, __shfl_xor_sync(0xffffffff, tm1, 2));
        float cor0 = exp2f((m0 - tm0) * LOG2E);
        float cor1 = exp2f((m1 - tm1) * LOG2E);
        m0 = tm0; m1 = tm1;
        float s0 = 0.f, s1 = 0.f;
        #pragma unroll
        for (int f = 0; f < 16; f++) {
            sf[f][0] = exp2f((sf[f][0] - m0) * LOG2E);
            sf[f][1] = exp2f((sf[f][1] - m0) * LOG2E);
            sf[f][2] = exp2f((sf[f][2] - m1) * LOG2E);
            sf[f][3] = exp2f((sf[f][3] - m1) * LOG2E);
            s0 += sf[f][0] + sf[f][1];
            s1 += sf[f][2] + sf[f][3];
        }
        s0 += __shfl_xor_sync(0xffffffff, s0, 1);
        s0 += __shfl_xor_sync(0xffffffff, s0, 2);
        s1 += __shfl_xor_sync(0xffffffff, s1, 1);
        s1 += __shfl_xor_sync(0xffffffff, s1, 2);
        l0 = l0 * cor0 + s0;
        l1 = l1 * cor1 + s1;
        #pragma unroll
        for (int f = 0; f < 16; f++) {
            of[f][0] *= cor0; of[f][1] *= cor0;
            of[f][2] *= cor1; of[f][3] *= cor1;
        }

        #pragma unroll
        for (int ks = 0; ks < 8; ks++) {
            uint32_t pah[4], pal[4];
            split2(sf[2*ks][0],   sf[2*ks][1],   pah[0], pal[0]);
            split2(sf[2*ks][2],   sf[2*ks][3],   pah[1], pal[1]);
            split2(sf[2*ks+1][0], sf[2*ks+1][1], pah[2], pal[2]);
            split2(sf[2*ks+1][2], sf[2*ks+1][3], pah[3], pal[3]);
            uint32_t vkey = (uint32_t)ks * 16 + v_krow;
            #pragma unroll
            for (int j16 = 0; j16 < 8; j16++) {
                uint32_t ncol = (uint32_t)j16 * 16 + v_ncol;
                uint32_t va = sb + A_SVH + (ncol >> 6) * 16384 + vkey * 128
                            + (((ncol & 63) * 2) ^ ((vkey & 7) * 16));
                uint32_t vh4[4], vl4[4];
                ldsm_x4_t(vh4[0], vh4[1], vh4[2], vh4[3], va);
                ldsm_x4_t(vl4[0], vl4[1], vl4[2], vl4[3], va + (A_SVL - A_SVH));
                mma_bf16(of[2*j16],   pah, vh4[0], vh4[1]);
                mma_bf16(of[2*j16+1], pah, vh4[2], vh4[3]);
                mma_bf16(of[2*j16],   pah, vl4[0], vl4[1]);
                mma_bf16(of[2*j16+1], pah, vl4[2], vl4[3]);
                mma_bf16(of[2*j16],   pal, vh4[0], vh4[1]);
                mma_bf16(of[2*j16+1], pal, vh4[2], vh4[3]);
            }
        }

        CP_WAIT(0);
        __syncthreads();
    }

    const float inv0 = 1.f / l0;
    const float inv1 = 1.f / l1;
    const int r0 = q0 + 16 * wid + (lane >> 2);
    const int cc = (lane & 3) * 2;
    #pragma unroll
    for (int f = 0; f < 16; f++) {
        int col = f * 8 + cc;
        uint32_t h0, lo0, h1, lo1;
        split2(of[f][0] * inv0, of[f][1] * inv0, h0, lo0);
        split2(of[f][2] * inv1, of[f][3] * inv1, h1, lo1);
        size_t o0 = hb + (size_t)r0 * HIDDEN + col;
        size_t o1 = hb + (size_t)(r0 + 8) * HIDDEN + col;
        *(uint32_t*)(AOh + o0) = h0;
        *(uint32_t*)(AOl + o0) = lo0;
        *(uint32_t*)(AOh + o1) = h1;
        *(uint32_t*)(AOl + o1) = lo1;
    }
}

// ------------------------------------------------------------------------------
extern "C" void kernel_launch(void* const* d_in, const int* in_sizes, int n_in,
                              void* d_out, int out_size)
{
    const float* x  = (const float*)d_in[0];
    const float* wq = (const float*)d_in[1];
    const float* wk = (const float*)d_in[2];
    const float* wv = (const float*)d_in[3];
    const float* wo = (const float*)d_in[4];
    float* out = (float*)d_out;

    __nv_bfloat16 *qh, *ql, *kh, *kl, *vh, *vl, *aoh, *aol, *xh, *xl;
    __nv_bfloat16 *wqh, *wql, *wkh, *wkl, *wvh, *wvl, *woh, *wol;
    cudaGetSymbolAddress((void**)&qh,  g_qh);  cudaGetSymbolAddress((void**)&ql,  g_ql);
    cudaGetSymbolAddress((void**)&kh,  g_kh);  cudaGetSymbolAddress((void**)&kl,  g_kl);
    cudaGetSymbolAddress((void**)&vh,  g_vh);  cudaGetSymbolAddress((void**)&vl,  g_vl);
    cudaGetSymbolAddress((void**)&aoh, g_aoh); cudaGetSymbolAddress((void**)&aol, g_aol);
    cudaGetSymbolAddress((void**)&xh,  g_xh);  cudaGetSymbolAddress((void**)&xl,  g_xl);
    cudaGetSymbolAddress((void**)&wqh, g_wqh); cudaGetSymbolAddress((void**)&wql, g_wql);
    cudaGetSymbolAddress((void**)&wkh, g_wkh); cudaGetSymbolAddress((void**)&wkl, g_wkl);
    cudaGetSymbolAddress((void**)&wvh, g_wvh); cudaGetSymbolAddress((void**)&wvl, g_wvl);
    cudaGetSymbolAddress((void**)&woh, g_woh); cudaGetSymbolAddress((void**)&wol, g_wol);

    cudaFuncSetAttribute(gemm_mma_3p, cudaFuncAttributeMaxDynamicSharedMemorySize,
                         SMEM_GEMM);
    cudaFuncSetAttribute(attn_mma, cudaFuncAttributeMaxDynamicSharedMemorySize,
                         SMEM_ATTN);

    // one fused convert launch for all 5 input tensors
    dim3 gcvt((HIDDEN * HIDDEN) / 4 / 256, 5);   // (16384, 5)
    cvt_hilo5<<<gcvt, 256>>>(
        (const float4*)x,  (__nv_bfloat162*)xh,  (__nv_bfloat162*)xl,
        (const float4*)wq, (__nv_bfloat162*)wqh, (__nv_bfloat162*)wql,
        (const float4*)wk, (__nv_bfloat162*)wkh, (__nv_bfloat162*)wkl,
        (const float4*)wv, (__nv_bfloat162*)wvh, (__nv_bfloat162*)wvl,
        (const float4*)wo, (__nv_bfloat162*)woh, (__nv_bfloat162*)wol);

    dim3 gg(HIDDEN / NT, MTOK / MT);   // (32, 64) = 2048 CTAs
    gemm_mma_3p<<<gg, 256, SMEM_GEMM>>>(xh, xl, wqh, wql, nullptr, qh, ql, QSCALE);
    gemm_mma_3p<<<gg, 256, SMEM_GEMM>>>(xh, xl, wkh, wkl, nullptr, kh, kl, 1.0f);
    gemm_mma_3p<<<gg, 256, SMEM_GEMM>>>(xh, xl, wvh, wvl, nullptr, vh, vl, 1.0f);

    dim3 ga(SEQ / 128, NHEADS, BATCH); // (16, 32, 2)
    attn_mma<<<ga, 256, SMEM_ATTN>>>(qh, ql, kh, kl, vh, vl, aoh, aol);

    gemm_mma_3p<<<gg, 256, SMEM_GEMM>>>(aoh, aol, woh, wol, out, nullptr, nullptr, 1.0f);
}

// round 14
// speedup vs baseline: 1.0331x; 1.0324x over previous
#include <cuda_runtime.h>
#include <cuda_bf16.h>
#include <math.h>
#include <stdint.h>

#define HIDDEN 4096
#define NHEADS 32
#define DK     128
#define BATCH  2
#define SEQ    2048
#define MTOK   (BATCH*SEQ)   // 4096

// GEMM tiling (mma.sync bf16): 64x128 CTA tile, 2-stage, 2 CTAs/SM
#define MT 64
#define NT 128
#define NCHUNK (HIDDEN / 64)   // 64
#define ST_A 8192              // 64 rows x 128B
#define ST_B 16384             // 128 rows x 128B
#define STAGE_BYTES (2*ST_A + 2*ST_B)   // 49152
#define SMEM_GEMM (2 * STAGE_BYTES)     // 98304 -> 2 CTAs/SM

// attention smem layout (bytes)
#define A_SQH 0
#define A_SQL 32768
#define A_SKH 65536
#define A_SKL 98304
#define A_SVH 131072
#define A_SVL 163840
#define SMEM_ATTN 196608

#define LOG2E 1.4426950408889634f
// Q epilogue scale: (1/sqrt(128)) * log2(e)  -> softmax runs in base 2 directly
#define QSCALE2 0.12754239511348782f

// ---------------- scratch ----------------------------------------------------
__device__ __nv_bfloat16 g_qh [MTOK * HIDDEN];
__device__ __nv_bfloat16 g_ql [MTOK * HIDDEN];
__device__ __nv_bfloat16 g_kh [MTOK * HIDDEN];
__device__ __nv_bfloat16 g_kl [MTOK * HIDDEN];
__device__ __nv_bfloat16 g_vh [MTOK * HIDDEN];
__device__ __nv_bfloat16 g_vl [MTOK * HIDDEN];
__device__ __nv_bfloat16 g_aoh[MTOK * HIDDEN];
__device__ __nv_bfloat16 g_aol[MTOK * HIDDEN];
__device__ __nv_bfloat16 g_xh [MTOK * HIDDEN];
__device__ __nv_bfloat16 g_xl [MTOK * HIDDEN];
__device__ __nv_bfloat16 g_wqh[HIDDEN * HIDDEN];
__device__ __nv_bfloat16 g_wql[HIDDEN * HIDDEN];
__device__ __nv_bfloat16 g_wkh[HIDDEN * HIDDEN];
__device__ __nv_bfloat16 g_wkl[HIDDEN * HIDDEN];
__device__ __nv_bfloat16 g_wvh[HIDDEN * HIDDEN];
__device__ __nv_bfloat16 g_wvl[HIDDEN * HIDDEN];
__device__ __nv_bfloat16 g_woh[HIDDEN * HIDDEN];
__device__ __nv_bfloat16 g_wol[HIDDEN * HIDDEN];

// ---------------- PTX helpers -------------------------------------------------
__device__ __forceinline__ uint32_t smem_u32(const void* p) {
    uint32_t a;
    asm("{ .reg .u64 t; cvta.to.shared.u64 t, %1; cvt.u32.u64 %0, t; }"
        : "=r"(a) : "l"(p));
    return a;
}
__device__ __forceinline__ void cp16(uint32_t dst, const void* src) {
    asm volatile("cp.async.cg.shared.global [%0], [%1], 16;"
                 :: "r"(dst), "l"(src) : "memory");
}
#define CP_COMMIT() asm volatile("cp.async.commit_group;" ::: "memory")
#define CP_WAIT(n)  asm volatile("cp.async.wait_group %0;" :: "n"(n) : "memory")

__device__ __forceinline__ void ldsm_x4(uint32_t& r0, uint32_t& r1,
                                        uint32_t& r2, uint32_t& r3, uint32_t a) {
    asm volatile("ldmatrix.sync.aligned.m8n8.x4.shared.b16 {%0,%1,%2,%3}, [%4];"
                 : "=r"(r0), "=r"(r1), "=r"(r2), "=r"(r3) : "r"(a));
}
__device__ __forceinline__ void ldsm_x4_t(uint32_t& r0, uint32_t& r1,
                                          uint32_t& r2, uint32_t& r3, uint32_t a) {
    asm volatile("ldmatrix.sync.aligned.m8n8.x4.trans.shared.b16 {%0,%1,%2,%3}, [%4];"
                 : "=r"(r0), "=r"(r1), "=r"(r2), "=r"(r3) : "r"(a));
}
__device__ __forceinline__ void mma_bf16(float* c, const uint32_t* a,
                                         uint32_t b0, uint32_t b1) {
    asm volatile(
        "mma.sync.aligned.m16n8k16.row.col.f32.bf16.bf16.f32 "
        "{%0,%1,%2,%3}, {%4,%5,%6,%7}, {%8,%9}, {%0,%1,%2,%3};"
        : "+f"(c[0]), "+f"(c[1]), "+f"(c[2]), "+f"(c[3])
        : "r"(a[0]), "r"(a[1]), "r"(a[2]), "r"(a[3]), "r"(b0), "r"(b1));
}
__device__ __forceinline__ uint32_t packbf2(__nv_bfloat16 a, __nv_bfloat16 b) {
    __nv_bfloat162 t = __halves2bfloat162(a, b);
    return *(uint32_t*)&t;
}
__device__ __forceinline__ void split2(float a, float b, uint32_t& hi, uint32_t& lo) {
    __nv_bfloat16 ha = __float2bfloat16(a), hb = __float2bfloat16(b);
    __nv_bfloat16 la = __float2bfloat16(a - __bfloat162float(ha));
    __nv_bfloat16 lb = __float2bfloat16(b - __bfloat162float(hb));
    hi = packbf2(ha, hb);
    lo = packbf2(la, lb);
}

// ---------------- fused fp32 -> bf16 hi/lo split (5 tensors, one launch) -------
__global__ __launch_bounds__(256)
void cvt_hilo5(const float4* __restrict__ s0, __nv_bfloat162* __restrict__ h0, __nv_bfloat162* __restrict__ l0,
               const float4* __restrict__ s1, __nv_bfloat162* __restrict__ h1, __nv_bfloat162* __restrict__ l1,
               const float4* __restrict__ s2, __nv_bfloat162* __restrict__ h2, __nv_bfloat162* __restrict__ l2,
               const float4* __restrict__ s3, __nv_bfloat162* __restrict__ h3, __nv_bfloat162* __restrict__ l3,
               const float4* __restrict__ s4, __nv_bfloat162* __restrict__ h4, __nv_bfloat162* __restrict__ l4)
{
    const int t = blockIdx.y;
    const float4* s = (t == 0) ? s0 : (t == 1) ? s1 : (t == 2) ? s2 : (t == 3) ? s3 : s4;
    __nv_bfloat162* h = (t == 0) ? h0 : (t == 1) ? h1 : (t == 2) ? h2 : (t == 3) ? h3 : h4;
    __nv_bfloat162* l = (t == 0) ? l0 : (t == 1) ? l1 : (t == 2) ? l2 : (t == 3) ? l3 : l4;

    size_t i = (size_t)blockIdx.x * 256 + threadIdx.x;
    float4 v = s[i];
    uint32_t a0, b0, a1, b1;
    split2(v.x, v.y, a0, b0);
    split2(v.z, v.w, a1, b1);
    ((uint32_t*)h)[2*i]   = a0;
    ((uint32_t*)h)[2*i+1] = a1;
    ((uint32_t*)l)[2*i]   = b0;
    ((uint32_t*)l)[2*i+1] = b1;
}

// ---------------- bf16 3-pass GEMM via mma.sync, 64x128 tile, 2 CTAs/SM --------
// C = (Ah+Al)[M,K] @ (Bh+Bl)[N,K]^T (drop Al*Bl).
// blockIdx.z selects the B/C set (fused QKV). If Cf: fp32 output (z must be 0).
__global__ __launch_bounds__(256, 2)
void gemm_mma_3p(const __nv_bfloat16* __restrict__ Ah, const __nv_bfloat16* __restrict__ Al,
                 const __nv_bfloat16* __restrict__ B0h, const __nv_bfloat16* __restrict__ B0l,
                 const __nv_bfloat16* __restrict__ B1h, const __nv_bfloat16* __restrict__ B1l,
                 const __nv_bfloat16* __restrict__ B2h, const __nv_bfloat16* __restrict__ B2l,
                 __nv_bfloat16* __restrict__ C0h, __nv_bfloat16* __restrict__ C0l,
                 __nv_bfloat16* __restrict__ C1h, __nv_bfloat16* __restrict__ C1l,
                 __nv_bfloat16* __restrict__ C2h, __nv_bfloat16* __restrict__ C2l,
                 float* __restrict__ Cf, float scale0)
{
    extern __shared__ __align__(1024) char smem[];
    const uint32_t sb = smem_u32(smem);
    const int tid  = threadIdx.x;
    const int wid  = tid >> 5;
    const int lane = tid & 31;
    const int bm   = blockIdx.y * MT;
    const int bn   = blockIdx.x * NT;
    const int z    = blockIdx.z;

    const __nv_bfloat16* Bh = (z == 0) ? B0h : (z == 1) ? B1h : B2h;
    const __nv_bfloat16* Bl = (z == 0) ? B0l : (z == 1) ? B1l : B2l;
    __nv_bfloat16* Ch = (z == 0) ? C0h : (z == 1) ? C1h : C2h;
    __nv_bfloat16* Cl = (z == 0) ? C0l : (z == 1) ? C1l : C2l;
    const float scale = (z == 0) ? scale0 : 1.0f;

    // warp grid: 2 (m) x 4 (n); warp tile 32x32
    const int wm0 = (wid & 1) * 32;
    const int wn0 = (wid >> 1) * 32;

    const char* gah = (const char*)Ah + (size_t)bm * (HIDDEN * 2);
    const char* gal = (const char*)Al + (size_t)bm * (HIDDEN * 2);
    const char* gbh = (const char*)Bh + (size_t)bn * (HIDDEN * 2);
    const char* gbl = (const char*)Bl + (size_t)bn * (HIDDEN * 2);

    const int a_r = lane & 15;
    const uint32_t a_k16 = (lane >> 4) * 16;
    uint32_t a_rb[2], a_xm[2];
    #pragma unroll
    for (int i = 0; i < 2; i++) {
        int row = wm0 + i * 16 + a_r;
        a_rb[i] = (uint32_t)row * 128;
        a_xm[i] = (uint32_t)(row & 7) * 16;
    }
    const int b_r = ((lane >> 4) & 1) * 8 + (lane & 7);
    const uint32_t b_k16 = ((lane >> 3) & 1) * 16;
    uint32_t b_rb[2], b_xm[2];
    #pragma unroll
    for (int j = 0; j < 2; j++) {
        int row = wn0 + j * 16 + b_r;
        b_rb[j] = (uint32_t)row * 128;
        b_xm[j] = (uint32_t)(row & 7) * 16;
    }

    float acc[2][4][4] = {};

    auto load_stage = [&](int s, int c) {
        const uint32_t st = sb + (uint32_t)s * STAGE_BYTES;
        const size_t cb = (size_t)c * 128;
        #pragma unroll
        for (int u = 0; u < 2; u++) {
            int idx = u * 256 + tid;
            uint32_t bo = (uint32_t)idx << 4;
            uint32_t sw = bo ^ ((bo >> 3) & 0x70);
            size_t go = (size_t)(idx >> 3) * (HIDDEN * 2) + (size_t)(idx & 7) * 16 + cb;
            cp16(st + sw, gah + go);
            cp16(st + ST_A + sw, gal + go);
        }
        #pragma unroll
        for (int u = 0; u < 4; u++) {
            int idx = u * 256 + tid;
            uint32_t bo = (uint32_t)idx << 4;
            uint32_t sw = bo ^ ((bo >> 3) & 0x70);
            size_t go = (size_t)(idx >> 3) * (HIDDEN * 2) + (size_t)(idx & 7) * 16 + cb;
            cp16(st + 2 * ST_A + sw, gbh + go);
            cp16(st + 2 * ST_A + ST_B + sw, gbl + go);
        }
        CP_COMMIT();
    };

    load_stage(0, 0);

    for (int c = 0; c < NCHUNK; c++) {
        CP_WAIT(0);
        __syncthreads();
        if (c + 1 < NCHUNK) load_stage((c + 1) & 1, c + 1);

        const uint32_t st  = sb + (uint32_t)(c & 1) * STAGE_BYTES;
        const uint32_t tAh = st;
        const uint32_t tAl = st + ST_A;
        const uint32_t tBh = st + 2 * ST_A;
        const uint32_t tBl = st + 2 * ST_A + ST_B;

        #pragma unroll
        for (int ks = 0; ks < 4; ks++) {
            const uint32_t ak = (uint32_t)ks * 32 + a_k16;
            const uint32_t bk = (uint32_t)ks * 32 + b_k16;

            uint32_t ah[2][4], al[2][4], bh[2][4], bl[2][4];
            #pragma unroll
            for (int i = 0; i < 2; i++) {
                uint32_t off = a_rb[i] + (ak ^ a_xm[i]);
                ldsm_x4(ah[i][0], ah[i][1], ah[i][2], ah[i][3], tAh + off);
                ldsm_x4(al[i][0], al[i][1], al[i][2], al[i][3], tAl + off);
            }
            #pragma unroll
            for (int j = 0; j < 2; j++) {
                uint32_t off = b_rb[j] + (bk ^ b_xm[j]);
                ldsm_x4(bh[j][0], bh[j][1], bh[j][2], bh[j][3], tBh + off);
                ldsm_x4(bl[j][0], bl[j][1], bl[j][2], bl[j][3], tBl + off);
            }
            #pragma unroll
            for (int i = 0; i < 2; i++)
                #pragma unroll
                for (int j = 0; j < 4; j++)
                    mma_bf16(acc[i][j], ah[i],
                             bh[j >> 1][(j & 1) * 2], bh[j >> 1][(j & 1) * 2 + 1]);
            #pragma unroll
            for (int i = 0; i < 2; i++)
                #pragma unroll
                for (int j = 0; j < 4; j++)
                    mma_bf16(acc[i][j], ah[i],
                             bl[j >> 1][(j & 1) * 2], bl[j >> 1][(j & 1) * 2 + 1]);
            #pragma unroll
            for (int i = 0; i < 2; i++)
                #pragma unroll
                for (int j = 0; j < 4; j++)
                    mma_bf16(acc[i][j], al[i],
                             bh[j >> 1][(j & 1) * 2], bh[j >> 1][(j & 1) * 2 + 1]);
        }
    }

    const int cr = lane >> 2;
    const int cc = (lane & 3) * 2;
    #pragma unroll
    for (int i = 0; i < 2; i++) {
        #pragma unroll
        for (int j = 0; j < 4; j++) {
            int row = bm + wm0 + i * 16 + cr;
            int col = bn + wn0 + j * 8 + cc;
            if (Cf) {
                *(float2*)(Cf + (size_t)row * HIDDEN + col) =
                    make_float2(acc[i][j][0], acc[i][j][1]);
                *(float2*)(Cf + (size_t)(row + 8) * HIDDEN + col) =
                    make_float2(acc[i][j][2], acc[i][j][3]);
            } else {
                uint32_t h0, l0, h1, l1;
                split2(acc[i][j][0] * scale, acc[i][j][1] * scale, h0, l0);
                split2(acc[i][j][2] * scale, acc[i][j][3] * scale, h1, l1);
                *(uint32_t*)(Ch + (size_t)row * HIDDEN + col)       = h0;
                *(uint32_t*)(Cl + (size_t)row * HIDDEN + col)       = l0;
                *(uint32_t*)(Ch + (size_t)(row + 8) * HIDDEN + col) = h1;
                *(uint32_t*)(Cl + (size_t)(row + 8) * HIDDEN + col) = l1;
            }
        }
    }
}

// ---------------- flash attention via mma.sync (split bf16, base-2 softmax) ----
// Q is pre-scaled by (1/sqrt(dk))*log2(e): scores are already in log2 domain.
__global__ __launch_bounds__(256)
void attn_mma(const __nv_bfloat16* __restrict__ Qh, const __nv_bfloat16* __restrict__ Ql,
              const __nv_bfloat16* __restrict__ Kh, const __nv_bfloat16* __restrict__ Kl,
              const __nv_bfloat16* __restrict__ Vh, const __nv_bfloat16* __restrict__ Vl,
              __nv_bfloat16* __restrict__ AOh, __nv_bfloat16* __restrict__ AOl)
{
    extern __shared__ __align__(1024) char smem[];
    const uint32_t sb = smem_u32(smem);
    const int tid  = threadIdx.x;
    const int wid  = tid >> 5;
    const int lane = tid & 31;
    const int q0   = blockIdx.x * 128;
    const int h    = blockIdx.y;
    const int b    = blockIdx.z;

    const size_t hb = ((size_t)b * SEQ) * HIDDEN + (size_t)h * DK;
    const char* gqh = (const char*)(Qh + hb + (size_t)q0 * HIDDEN);
    const char* gql = (const char*)(Ql + hb + (size_t)q0 * HIDDEN);
    const char* gkh = (const char*)(Kh + hb);
    const char* gkl = (const char*)(Kl + hb);
    const char* gvh = (const char*)(Vh + hb);
    const char* gvl = (const char*)(Vl + hb);

    auto load_tile = [&](uint32_t soff, const char* g) {
        #pragma unroll
        for (int r = 0; r < 8; r++) {
            int idx = r * 256 + tid;
            int row = idx >> 4, u = idx & 15;
            uint32_t sa = sb + soff + (uint32_t)(u >> 3) * 16384
                        + (uint32_t)row * 128
                        + (((uint32_t)(u & 7) * 16) ^ ((uint32_t)(row & 7) * 16));
            cp16(sa, g + (size_t)row * (HIDDEN * 2) + (size_t)u * 16);
        }
    };

    load_tile(A_SQH, gqh);
    load_tile(A_SQL, gql);
    load_tile(A_SKH, gkh);
    load_tile(A_SKL, gkl);
    CP_COMMIT();
    CP_WAIT(0);
    __syncthreads();

    float of[16][4] = {};
    float m0 = -INFINITY, m1 = -INFINITY, l0 = 0.f, l1 = 0.f;

    const uint32_t q_row = (uint32_t)(16 * wid + (lane & 15));
    const uint32_t q_kof = (uint32_t)(lane >> 4) * 16;
    const uint32_t q_xm  = (q_row & 7) * 16;
    const uint32_t q_rb  = q_row * 128;

    const uint32_t k_r   = (uint32_t)(((lane >> 4) & 1) * 8 + (lane & 7));
    const uint32_t k_kof = (uint32_t)((lane >> 3) & 1) * 16;

    const int v_grp  = lane >> 3;
    const uint32_t v_krow = (uint32_t)((v_grp & 1) * 8 + (lane & 7));
    const uint32_t v_ncol = (uint32_t)((v_grp >> 1) * 8);

    for (int t = 0; t < 16; t++) {
        load_tile(A_SVH, gvh + (size_t)t * 128 * (HIDDEN * 2));
        load_tile(A_SVL, gvl + (size_t)t * 128 * (HIDDEN * 2));
        CP_COMMIT();

        float sf[16][4] = {};
        #pragma unroll
        for (int ks = 0; ks < 8; ks++) {
            uint32_t qa = sb + A_SQH + (uint32_t)(ks >> 2) * 16384 + q_rb
                        + ((((uint32_t)(ks & 3) * 32) + q_kof) ^ q_xm);
            uint32_t qh4[4], ql4[4];
            ldsm_x4(qh4[0], qh4[1], qh4[2], qh4[3], qa);
            ldsm_x4(ql4[0], ql4[1], ql4[2], ql4[3], qa + (A_SQL - A_SQH));
            #pragma unroll
            for (int j16 = 0; j16 < 8; j16++) {
                uint32_t krow = (uint32_t)j16 * 16 + k_r;
                uint32_t ka = sb + A_SKH + (uint32_t)(ks >> 2) * 16384 + krow * 128
                            + ((((uint32_t)(ks & 3) * 32) + k_kof) ^ ((krow & 7) * 16));
                uint32_t kh4[4], kl4[4];
                ldsm_x4(kh4[0], kh4[1], kh4[2], kh4[3], ka);
                ldsm_x4(kl4[0], kl4[1], kl4[2], kl4[3], ka + (A_SKL - A_SKH));
                mma_bf16(sf[2*j16],   qh4, kh4[0], kh4[1]);
                mma_bf16(sf[2*j16+1], qh4, kh4[2], kh4[3]);
                mma_bf16(sf[2*j16],   qh4, kl4[0], kl4[1]);
                mma_bf16(sf[2*j16+1], qh4, kl4[2], kl4[3]);
                mma_bf16(sf[2*j16],   ql4, kh4[0], kh4[1]);
                mma_bf16(sf[2*j16+1], ql4, kh4[2], kh4[3]);
            }
        }

        CP_WAIT(0);
        __syncthreads();

        if (t + 1 < 16) {
            load_tile(A_SKH, gkh + (size_t)(t + 1) * 128 * (HIDDEN * 2));
            load_tile(A_SKL, gkl + (size_t)(t + 1) * 128 * (HIDDEN * 2));
            CP_COMMIT();
        }

        // ---- online softmax, base 2 (scores already in log2 domain) ----
        float tm0 = m0, tm1 = m1;
        #pragma unroll
        for (int f = 0; f < 16; f++) {
            tm0 = fmaxf(tm0, fmaxf(sf[f][0], sf[f][1]));
            tm1 = fmaxf(tm1, fmaxf(sf[f][2], sf[f][3]));
        }
        tm0 = fmaxf(tm0, __shfl_xor_sync(0xffffffff, tm0, 1));
        tm0 = fmaxf(tm0, __shfl_xor_sync(0xffffffff, tm0, 2));
        tm1 = fmaxf(tm1, __shfl_xor_sync(0xffffffff, tm1, 1));
        tm1 = fmaxf(tm1, __shfl_xor_sync(0xffffffff, tm1, 2));
        float cor0 = exp2f(m0 - tm0);
        float cor1 = exp2f(m1 - tm1);
        m0 = tm0; m1 = tm1;
        float s0 = 0.f, s1 = 0.f;
        #pragma unroll
        for (int f = 0; f < 16; f++) {
            sf[f][0] = exp2f(sf[f][0] - m0);
            sf[f][1] = exp2f(sf[f][1] - m0);
            sf[f][2] = exp2f(sf[f][2] - m1);
            sf[f][3] = exp2f(sf[f][3] - m1);
            s0 += sf[f][0] + sf[f][1];
            s1 += sf[f][2] + sf[f][3];
        }
        s0 += __shfl_xor_sync(0xffffffff, s0, 1);
        s0 += __shfl_xor_sync(0xffffffff, s0, 2);
        s1 += __shfl_xor_sync(0xffffffff, s1, 1);
        s1 += __shfl_xor_sync(0xffffffff, s1, 2);
        l0 = l0 * cor0 + s0;
        l1 = l1 * cor1 + s1;
        #pragma unroll
        for (int f = 0; f < 16; f++) {
            of[f][0] *= cor0; of[f][1] *= cor0;
            of[f][2] *= cor1; of[f][3] *= cor1;
        }

        #pragma unroll
        for (int ks = 0; ks < 8; ks++) {
            uint32_t pah[4], pal[4];
            split2(sf[2*ks][0],   sf[2*ks][1],   pah[0], pal[0]);
            split2(sf[2*ks][2],   sf[2*ks][3],   pah[1], pal[1]);
            split2(sf[2*ks+1][0], sf[2*ks+1][1], pah[2], pal[2]);
            split2(sf[2*ks+1][2], sf[2*ks+1][3], pah[3], pal[3]);
            uint32_t vkey = (uint32_t)ks * 16 + v_krow;
            #pragma unroll
            for (int j16 = 0; j16 < 8; j16++) {
                uint32_t ncol = (uint32_t)j16 * 16 + v_ncol;
                uint32_t va = sb + A_SVH + (ncol >> 6) * 16384 + vkey * 128
                            + (((ncol & 63) * 2) ^ ((vkey & 7) * 16));
                uint32_t vh4[4], vl4[4];
                ldsm_x4_t(vh4[0], vh4[1], vh4[2], vh4[3], va);
                ldsm_x4_t(vl4[0], vl4[1], vl4[2], vl4[3], va + (A_SVL - A_SVH));
                mma_bf16(of[2*j16],   pah, vh4[0], vh4[1]);
                mma_bf16(of[2*j16+1], pah, vh4[2], vh4[3]);
                mma_bf16(of[2*j16],   pah, vl4[0], vl4[1]);
                mma_bf16(of[2*j16+1], pah, vl4[2], vl4[3]);
                mma_bf16(of[2*j16],   pal, vh4[0], vh4[1]);
                mma_bf16(of[2*j16+1], pal, vh4[2], vh4[3]);
            }
        }

        CP_WAIT(0);
        __syncthreads();
    }

    const float inv0 = 1.f / l0;
    const float inv1 = 1.f / l1;
    const int r0 = q0 + 16 * wid + (lane >> 2);
    const int cc = (lane & 3) * 2;
    #pragma unroll
    for (int f = 0; f < 16; f++) {
        int col = f * 8 + cc;
        uint32_t h0, lo0, h1, lo1;
        split2(of[f][0] * inv0, of[f][1] * inv0, h0, lo0);
        split2(of[f][2] * inv1, of[f][3] * inv1, h1, lo1);
        size_t o0 = hb + (size_t)r0 * HIDDEN + col;
        size_t o1 = hb + (size_t)(r0 + 8) * HIDDEN + col;
        *(uint32_t*)(AOh + o0) = h0;
        *(uint32_t*)(AOl + o0) = lo0;
        *(uint32_t*)(AOh + o1) = h1;
        *(uint32_t*)(AOl + o1) = lo1;
    }
}

// ------------------------------------------------------------------------------
extern "C" void kernel_launch(void* const* d_in, const int* in_sizes, int n_in,
                              void* d_out, int out_size)
{
    const float* x  = (const float*)d_in[0];
    const float* wq = (const float*)d_in[1];
    const float* wk = (const float*)d_in[2];
    const float* wv = (const float*)d_in[3];
    const float* wo = (const float*)d_in[4];
    float* out = (float*)d_out;

    __nv_bfloat16 *qh, *ql, *kh, *kl, *vh, *vl, *aoh, *aol, *xh, *xl;
    __nv_bfloat16 *wqh, *wql, *wkh, *wkl, *wvh, *wvl, *woh, *wol;
    cudaGetSymbolAddress((void**)&qh,  g_qh);  cudaGetSymbolAddress((void**)&ql,  g_ql);
    cudaGetSymbolAddress((void**)&kh,  g_kh);  cudaGetSymbolAddress((void**)&kl,  g_kl);
    cudaGetSymbolAddress((void**)&vh,  g_vh);  cudaGetSymbolAddress((void**)&vl,  g_vl);
    cudaGetSymbolAddress((void**)&aoh, g_aoh); cudaGetSymbolAddress((void**)&aol, g_aol);
    cudaGetSymbolAddress((void**)&xh,  g_xh);  cudaGetSymbolAddress((void**)&xl,  g_xl);
    cudaGetSymbolAddress((void**)&wqh, g_wqh); cudaGetSymbolAddress((void**)&wql, g_wql);
    cudaGetSymbolAddress((void**)&wkh, g_wkh); cudaGetSymbolAddress((void**)&wkl, g_wkl);
    cudaGetSymbolAddress((void**)&wvh, g_wvh); cudaGetSymbolAddress((void**)&wvl, g_wvl);
    cudaGetSymbolAddress((void**)&woh, g_woh); cudaGetSymbolAddress((void**)&wol, g_wol);

    cudaFuncSetAttribute(gemm_mma_3p, cudaFuncAttributeMaxDynamicSharedMemorySize,
                         SMEM_GEMM);
    cudaFuncSetAttribute(attn_mma, cudaFuncAttributeMaxDynamicSharedMemorySize,
                         SMEM_ATTN);

    // one fused convert launch for all 5 input tensors
    dim3 gcvt((HIDDEN * HIDDEN) / 4 / 256, 5);   // (16384, 5)
    cvt_hilo5<<<gcvt, 256>>>(
        (const float4*)x,  (__nv_bfloat162*)xh,  (__nv_bfloat162*)xl,
        (const float4*)wq, (__nv_bfloat162*)wqh, (__nv_bfloat162*)wql,
        (const float4*)wk, (__nv_bfloat162*)wkh, (__nv_bfloat162*)wkl,
        (const float4*)wv, (__nv_bfloat162*)wvh, (__nv_bfloat162*)wvl,
        (const float4*)wo, (__nv_bfloat162*)woh, (__nv_bfloat162*)wol);

    // fused Q/K/V projections: z selects weight + destination; Q pre-scaled for base-2 softmax
    dim3 gqkv(HIDDEN / NT, MTOK / MT, 3);   // (32, 64, 3)
    gemm_mma_3p<<<gqkv, 256, SMEM_GEMM>>>(
        xh, xl, wqh, wql, wkh, wkl, wvh, wvl,
        qh, ql, kh, kl, vh, vl, nullptr, QSCALE2);

    dim3 ga(SEQ / 128, NHEADS, BATCH);      // (16, 32, 2)
    attn_mma<<<ga, 256, SMEM_ATTN>>>(qh, ql, kh, kl, vh, vl, aoh, aol);

    // output projection: fp32 result
    dim3 go(HIDDEN / NT, MTOK / MT, 1);     // (32, 64, 1)
    gemm_mma_3p<<<go, 256, SMEM_GEMM>>>(
        aoh, aol, woh, wol, nullptr, nullptr, nullptr, nullptr,
        nullptr, nullptr, nullptr, nullptr, nullptr, nullptr, out, 1.0f);
}

// round 15
// speedup vs baseline: 1.3478x; 1.3046x over previous
#include <cuda_runtime.h>
#include <cuda_bf16.h>
#include <cuda_fp16.h>
#include <math.h>
#include <stdint.h>

#define HIDDEN 4096
#define NHEADS 32
#define DK     128
#define BATCH  2
#define SEQ    2048
#define MTOK   (BATCH*SEQ)   // 4096

// GEMM tiling: 64x128 CTA tile, 2-stage, 2 CTAs/SM
#define MT 64
#define NT 128
#define NCHUNK (HIDDEN / 64)   // 64
#define ST_A 8192              // 64 rows x 128B

// fp16 2-pass stage: Ah, Al, Bh              -> 32KB
#define STG2 (2*ST_A + 16384)
#define SMEM_G2 (2 * STG2)                    // 65536
// bf16 3-pass stage: Ah, Al, Bh, Bl          -> 48KB
#define STG3 (2*ST_A + 2*16384)
#define SMEM_G3 (2 * STG3)                    // 98304

// attention smem (fp16): Qh, Kh, Kl, Vh, Vl  (32KB each)
#define A_SQH 0
#define A_SKH 32768
#define A_SKL 65536
#define A_SVH 98304
#define A_SVL 131072
#define SMEM_ATTN 163840

// Q epilogue scale: (1/sqrt(128)) * log2(e)  -> softmax runs in base 2
#define QSCALE2 0.12754239511348782f

// ---------------- scratch ----------------------------------------------------
__device__ __half g_qh [MTOK * HIDDEN];
__device__ __half g_ql [MTOK * HIDDEN];
__device__ __half g_kh [MTOK * HIDDEN];
__device__ __half g_kl [MTOK * HIDDEN];
__device__ __half g_vh [MTOK * HIDDEN];
__device__ __half g_vl [MTOK * HIDDEN];
__device__ __half g_xh [MTOK * HIDDEN];
__device__ __half g_xl [MTOK * HIDDEN];
__device__ __half g_wqh[HIDDEN * HIDDEN];
__device__ __half g_wkh[HIDDEN * HIDDEN];
__device__ __half g_wvh[HIDDEN * HIDDEN];
__device__ __nv_bfloat16 g_aoh[MTOK * HIDDEN];
__device__ __nv_bfloat16 g_aol[MTOK * HIDDEN];
__device__ __nv_bfloat16 g_woh[HIDDEN * HIDDEN];
__device__ __nv_bfloat16 g_wol[HIDDEN * HIDDEN];

// ---------------- PTX helpers -------------------------------------------------
__device__ __forceinline__ uint32_t smem_u32(const void* p) {
    uint32_t a;
    asm("{ .reg .u64 t; cvta.to.shared.u64 t, %1; cvt.u32.u64 %0, t; }"
        : "=r"(a) : "l"(p));
    return a;
}
__device__ __forceinline__ void cp16(uint32_t dst, const void* src) {
    asm volatile("cp.async.cg.shared.global [%0], [%1], 16;"
                 :: "r"(dst), "l"(src) : "memory");
}
#define CP_COMMIT() asm volatile("cp.async.commit_group;" ::: "memory")
#define CP_WAIT(n)  asm volatile("cp.async.wait_group %0;" :: "n"(n) : "memory")

__device__ __forceinline__ void ldsm_x4(uint32_t& r0, uint32_t& r1,
                                        uint32_t& r2, uint32_t& r3, uint32_t a) {
    asm volatile("ldmatrix.sync.aligned.m8n8.x4.shared.b16 {%0,%1,%2,%3}, [%4];"
                 : "=r"(r0), "=r"(r1), "=r"(r2), "=r"(r3) : "r"(a));
}
__device__ __forceinline__ void ldsm_x4_t(uint32_t& r0, uint32_t& r1,
                                          uint32_t& r2, uint32_t& r3, uint32_t a) {
    asm volatile("ldmatrix.sync.aligned.m8n8.x4.trans.shared.b16 {%0,%1,%2,%3}, [%4];"
                 : "=r"(r0), "=r"(r1), "=r"(r2), "=r"(r3) : "r"(a));
}
__device__ __forceinline__ void mma_bf16(float* c, const uint32_t* a,
                                         uint32_t b0, uint32_t b1) {
    asm volatile(
        "mma.sync.aligned.m16n8k16.row.col.f32.bf16.bf16.f32 "
        "{%0,%1,%2,%3}, {%4,%5,%6,%7}, {%8,%9}, {%0,%1,%2,%3};"
        : "+f"(c[0]), "+f"(c[1]), "+f"(c[2]), "+f"(c[3])
        : "r"(a[0]), "r"(a[1]), "r"(a[2]), "r"(a[3]), "r"(b0), "r"(b1));
}
__device__ __forceinline__ void mma_f16(float* c, const uint32_t* a,
                                        uint32_t b0, uint32_t b1) {
    asm volatile(
        "mma.sync.aligned.m16n8k16.row.col.f32.f16.f16.f32 "
        "{%0,%1,%2,%3}, {%4,%5,%6,%7}, {%8,%9}, {%0,%1,%2,%3};"
        : "+f"(c[0]), "+f"(c[1]), "+f"(c[2]), "+f"(c[3])
        : "r"(a[0]), "r"(a[1]), "r"(a[2]), "r"(a[3]), "r"(b0), "r"(b1));
}
// bf16 split (for wo / attention-out / O-proj path)
__device__ __forceinline__ void split2b(float a, float b, uint32_t& hi, uint32_t& lo) {
    __nv_bfloat16 ha = __float2bfloat16(a), hb = __float2bfloat16(b);
    __nv_bfloat16 la = __float2bfloat16(a - __bfloat162float(ha));
    __nv_bfloat16 lb = __float2bfloat16(b - __bfloat162float(hb));
    __nv_bfloat162 H = __halves2bfloat162(ha, hb), L = __halves2bfloat162(la, lb);
    hi = *(uint32_t*)&H; lo = *(uint32_t*)&L;
}
// fp16 split (for x / q / k / v)
__device__ __forceinline__ void split2h(float a, float b, uint32_t& hi, uint32_t& lo) {
    __half ha = __float2half_rn(a), hb = __float2half_rn(b);
    __half la = __float2half_rn(a - __half2float(ha));
    __half lb = __float2half_rn(b - __half2float(hb));
    __half2 H = __halves2half2(ha, hb), L = __halves2half2(la, lb);
    hi = *(uint32_t*)&H; lo = *(uint32_t*)&L;
}
__device__ __forceinline__ uint32_t pack2h(float a, float b) {
    __half2 t = __floats2half2_rn(a, b);
    return *(uint32_t*)&t;
}

// ---------------- fused fp32 -> split (5 tensors; wo -> bf16, rest -> fp16) ----
__global__ __launch_bounds__(256)
void cvt5(const float4* __restrict__ s0, uint32_t* __restrict__ h0, uint32_t* __restrict__ l0,
          const float4* __restrict__ s1, uint32_t* __restrict__ h1, uint32_t* __restrict__ l1,
          const float4* __restrict__ s2, uint32_t* __restrict__ h2, uint32_t* __restrict__ l2,
          const float4* __restrict__ s3, uint32_t* __restrict__ h3, uint32_t* __restrict__ l3,
          const float4* __restrict__ s4, uint32_t* __restrict__ h4, uint32_t* __restrict__ l4)
{
    const int t = blockIdx.y;
    const float4* s = (t == 0) ? s0 : (t == 1) ? s1 : (t == 2) ? s2 : (t == 3) ? s3 : s4;
    uint32_t* h = (t == 0) ? h0 : (t == 1) ? h1 : (t == 2) ? h2 : (t == 3) ? h3 : h4;
    uint32_t* l = (t == 0) ? l0 : (t == 1) ? l1 : (t == 2) ? l2 : (t == 3) ? l3 : l4;

    size_t i = (size_t)blockIdx.x * 256 + threadIdx.x;
    float4 v = s[i];
    uint32_t a0, b0, a1, b1;
    if (t == 4) {   // wo -> bf16 hi/lo
        split2b(v.x, v.y, a0, b0);
        split2b(v.z, v.w, a1, b1);
    } else {        // x, wq, wk, wv -> fp16 hi/lo
        split2h(v.x, v.y, a0, b0);
        split2h(v.z, v.w, a1, b1);
    }
    h[2*i]   = a0;
    h[2*i+1] = a1;
    l[2*i]   = b0;
    l[2*i+1] = b1;
}

// ---------------- fp16 2-pass GEMM (QKV fused): C = (Ah+Al) @ Bh^T --------------
// Error = A @ Bl (dropped) ~ 2^-12 incoherent. All kept operands normal-range.
__global__ __launch_bounds__(256, 2)
void gemm_f16_2p(const __half* __restrict__ Ah, const __half* __restrict__ Al,
                 const __half* __restrict__ B0h, const __half* __restrict__ B1h,
                 const __half* __restrict__ B2h,
                 __half* __restrict__ C0h, __half* __restrict__ C0l,
                 __half* __restrict__ C1h, __half* __restrict__ C1l,
                 __half* __restrict__ C2h, __half* __restrict__ C2l,
                 float scale0)
{
    extern __shared__ __align__(1024) char smem[];
    const uint32_t sb = smem_u32(smem);
    const int tid  = threadIdx.x;
    const int wid  = tid >> 5;
    const int lane = tid & 31;
    const int bm   = blockIdx.y * MT;
    const int bn   = blockIdx.x * NT;
    const int z    = blockIdx.z;

    const __half* Bh = (z == 0) ? B0h : (z == 1) ? B1h : B2h;
    __half* Ch = (z == 0) ? C0h : (z == 1) ? C1h : C2h;
    __half* Cl = (z == 0) ? C0l : (z == 1) ? C1l : C2l;
    const float scale = (z == 0) ? scale0 : 1.0f;

    const int wm0 = (wid & 1) * 32;
    const int wn0 = (wid >> 1) * 32;

    const char* gah = (const char*)Ah + (size_t)bm * (HIDDEN * 2);
    const char* gal = (const char*)Al + (size_t)bm * (HIDDEN * 2);
    const char* gbh = (const char*)Bh + (size_t)bn * (HIDDEN * 2);

    const int a_r = lane & 15;
    const uint32_t a_k16 = (lane >> 4) * 16;
    uint32_t a_rb[2], a_xm[2];
    #pragma unroll
    for (int i = 0; i < 2; i++) {
        int row = wm0 + i * 16 + a_r;
        a_rb[i] = (uint32_t)row * 128;
        a_xm[i] = (uint32_t)(row & 7) * 16;
    }
    const int b_r = ((lane >> 4) & 1) * 8 + (lane & 7);
    const uint32_t b_k16 = ((lane >> 3) & 1) * 16;
    uint32_t b_rb[2], b_xm[2];
    #pragma unroll
    for (int j = 0; j < 2; j++) {
        int row = wn0 + j * 16 + b_r;
        b_rb[j] = (uint32_t)row * 128;
        b_xm[j] = (uint32_t)(row & 7) * 16;
    }

    float acc[2][4][4] = {};

    auto load_stage = [&](int s, int c) {
        const uint32_t st = sb + (uint32_t)s * STG2;
        const size_t cb = (size_t)c * 128;
        #pragma unroll
        for (int u = 0; u < 2; u++) {
            int idx = u * 256 + tid;
            uint32_t bo = (uint32_t)idx << 4;
            uint32_t sw = bo ^ ((bo >> 3) & 0x70);
            size_t go = (size_t)(idx >> 3) * (HIDDEN * 2) + (size_t)(idx & 7) * 16 + cb;
            cp16(st + sw, gah + go);
            cp16(st + ST_A + sw, gal + go);
        }
        #pragma unroll
        for (int u = 0; u < 4; u++) {
            int idx = u * 256 + tid;
            uint32_t bo = (uint32_t)idx << 4;
            uint32_t sw = bo ^ ((bo >> 3) & 0x70);
            size_t go = (size_t)(idx >> 3) * (HIDDEN * 2) + (size_t)(idx & 7) * 16 + cb;
            cp16(st + 2 * ST_A + sw, gbh + go);
        }
        CP_COMMIT();
    };

    load_stage(0, 0);

    for (int c = 0; c < NCHUNK; c++) {
        CP_WAIT(0);
        __syncthreads();
        if (c + 1 < NCHUNK) load_stage((c + 1) & 1, c + 1);

        const uint32_t st  = sb + (uint32_t)(c & 1) * STG2;
        const uint32_t tAh = st;
        const uint32_t tAl = st + ST_A;
        const uint32_t tBh = st + 2 * ST_A;

        #pragma unroll
        for (int ks = 0; ks < 4; ks++) {
            const uint32_t ak = (uint32_t)ks * 32 + a_k16;
            const uint32_t bk = (uint32_t)ks * 32 + b_k16;

            uint32_t ah[2][4], al[2][4], bh[2][4];
            #pragma unroll
            for (int i = 0; i < 2; i++) {
                uint32_t off = a_rb[i] + (ak ^ a_xm[i]);
                ldsm_x4(ah[i][0], ah[i][1], ah[i][2], ah[i][3], tAh + off);
                ldsm_x4(al[i][0], al[i][1], al[i][2], al[i][3], tAl + off);
            }
            #pragma unroll
            for (int j = 0; j < 2; j++) {
                uint32_t off = b_rb[j] + (bk ^ b_xm[j]);
                ldsm_x4(bh[j][0], bh[j][1], bh[j][2], bh[j][3], tBh + off);
            }
            #pragma unroll
            for (int i = 0; i < 2; i++)
                #pragma unroll
                for (int j = 0; j < 4; j++)
                    mma_f16(acc[i][j], ah[i],
                            bh[j >> 1][(j & 1) * 2], bh[j >> 1][(j & 1) * 2 + 1]);
            #pragma unroll
            for (int i = 0; i < 2; i++)
                #pragma unroll
                for (int j = 0; j < 4; j++)
                    mma_f16(acc[i][j], al[i],
                            bh[j >> 1][(j & 1) * 2], bh[j >> 1][(j & 1) * 2 + 1]);
        }
    }

    const int cr = lane >> 2;
    const int cc = (lane & 3) * 2;
    #pragma unroll
    for (int i = 0; i < 2; i++) {
        #pragma unroll
        for (int j = 0; j < 4; j++) {
            int row = bm + wm0 + i * 16 + cr;
            int col = bn + wn0 + j * 8 + cc;
            uint32_t h0, l0, h1, l1;
            split2h(acc[i][j][0] * scale, acc[i][j][1] * scale, h0, l0);
            split2h(acc[i][j][2] * scale, acc[i][j][3] * scale, h1, l1);
            *(uint32_t*)(Ch + (size_t)row * HIDDEN + col)       = h0;
            *(uint32_t*)(Cl + (size_t)row * HIDDEN + col)       = l0;
            *(uint32_t*)(Ch + (size_t)(row + 8) * HIDDEN + col) = h1;
            *(uint32_t*)(Cl + (size_t)(row + 8) * HIDDEN + col) = l1;
        }
    }
}

// ---------------- bf16 3-pass GEMM (O-projection): fp32 out --------------------
__global__ __launch_bounds__(256, 2)
void gemm_bf16_3p(const __nv_bfloat16* __restrict__ Ah, const __nv_bfloat16* __restrict__ Al,
                  const __nv_bfloat16* __restrict__ Bh, const __nv_bfloat16* __restrict__ Bl,
                  float* __restrict__ Cf)
{
    extern __shared__ __align__(1024) char smem[];
    const uint32_t sb = smem_u32(smem);
    const int tid  = threadIdx.x;
    const int wid  = tid >> 5;
    const int lane = tid & 31;
    const int bm   = blockIdx.y * MT;
    const int bn   = blockIdx.x * NT;

    const int wm0 = (wid & 1) * 32;
    const int wn0 = (wid >> 1) * 32;

    const char* gah = (const char*)Ah + (size_t)bm * (HIDDEN * 2);
    const char* gal = (const char*)Al + (size_t)bm * (HIDDEN * 2);
    const char* gbh = (const char*)Bh + (size_t)bn * (HIDDEN * 2);
    const char* gbl = (const char*)Bl + (size_t)bn * (HIDDEN * 2);

    const int a_r = lane & 15;
    const uint32_t a_k16 = (lane >> 4) * 16;
    uint32_t a_rb[2], a_xm[2];
    #pragma unroll
    for (int i = 0; i < 2; i++) {
        int row = wm0 + i * 16 + a_r;
        a_rb[i] = (uint32_t)row * 128;
        a_xm[i] = (uint32_t)(row & 7) * 16;
    }
    const int b_r = ((lane >> 4) & 1) * 8 + (lane & 7);
    const uint32_t b_k16 = ((lane >> 3) & 1) * 16;
    uint32_t b_rb[2], b_xm[2];
    #pragma unroll
    for (int j = 0; j < 2; j++) {
        int row = wn0 + j * 16 + b_r;
        b_rb[j] = (uint32_t)row * 128;
        b_xm[j] = (uint32_t)(row & 7) * 16;
    }

    float acc[2][4][4] = {};

    auto load_stage = [&](int s, int c) {
        const uint32_t st = sb + (uint32_t)s * STG3;
        const size_t cb = (size_t)c * 128;
        #pragma unroll
        for (int u = 0; u < 2; u++) {
            int idx = u * 256 + tid;
            uint32_t bo = (uint32_t)idx << 4;
            uint32_t sw = bo ^ ((bo >> 3) & 0x70);
            size_t go = (size_t)(idx >> 3) * (HIDDEN * 2) + (size_t)(idx & 7) * 16 + cb;
            cp16(st + sw, gah + go);
            cp16(st + ST_A + sw, gal + go);
        }
        #pragma unroll
        for (int u = 0; u < 4; u++) {
            int idx = u * 256 + tid;
            uint32_t bo = (uint32_t)idx << 4;
            uint32_t sw = bo ^ ((bo >> 3) & 0x70);
            size_t go = (size_t)(idx >> 3) * (HIDDEN * 2) + (size_t)(idx & 7) * 16 + cb;
            cp16(st + 2 * ST_A + sw, gbh + go);
            cp16(st + 2 * ST_A + 16384 + sw, gbl + go);
        }
        CP_COMMIT();
    };

    load_stage(0, 0);

    for (int c = 0; c < NCHUNK; c++) {
        CP_WAIT(0);
        __syncthreads();
        if (c + 1 < NCHUNK) load_stage((c + 1) & 1, c + 1);

        const uint32_t st  = sb + (uint32_t)(c & 1) * STG3;
        const uint32_t tAh = st;
        const uint32_t tAl = st + ST_A;
        const uint32_t tBh = st + 2 * ST_A;
        const uint32_t tBl = st + 2 * ST_A + 16384;

        #pragma unroll
        for (int ks = 0; ks < 4; ks++) {
            const uint32_t ak = (uint32_t)ks * 32 + a_k16;
            const uint32_t bk = (uint32_t)ks * 32 + b_k16;

            uint32_t ah[2][4], al[2][4], bh[2][4], bl[2][4];
            #pragma unroll
            for (int i = 0; i < 2; i++) {
                uint32_t off = a_rb[i] + (ak ^ a_xm[i]);
                ldsm_x4(ah[i][0], ah[i][1], ah[i][2], ah[i][3], tAh + off);
                ldsm_x4(al[i][0], al[i][1], al[i][2], al[i][3], tAl + off);
            }
            #pragma unroll
            for (int j = 0; j < 2; j++) {
                uint32_t off = b_rb[j] + (bk ^ b_xm[j]);
                ldsm_x4(bh[j][0], bh[j][1], bh[j][2], bh[j][3], tBh + off);
                ldsm_x4(bl[j][0], bl[j][1], bl[j][2], bl[j][3], tBl + off);
            }
            #pragma unroll
            for (int i = 0; i < 2; i++)
                #pragma unroll
                for (int j = 0; j < 4; j++)
                    mma_bf16(acc[i][j], ah[i],
                             bh[j >> 1][(j & 1) * 2], bh[j >> 1][(j & 1) * 2 + 1]);
            #pragma unroll
            for (int i = 0; i < 2; i++)
                #pragma unroll
                for (int j = 0; j < 4; j++)
                    mma_bf16(acc[i][j], ah[i],
                             bl[j >> 1][(j & 1) * 2], bl[j >> 1][(j & 1) * 2 + 1]);
            #pragma unroll
            for (int i = 0; i < 2; i++)
                #pragma unroll
                for (int j = 0; j < 4; j++)
                    mma_bf16(acc[i][j], al[i],
                             bh[j >> 1][(j & 1) * 2], bh[j >> 1][(j & 1) * 2 + 1]);
        }
    }

    const int cr = lane >> 2;
    const int cc = (lane & 3) * 2;
    #pragma unroll
    for (int i = 0; i < 2; i++) {
        #pragma unroll
        for (int j = 0; j < 4; j++) {
            int row = bm + wm0 + i * 16 + cr;
            int col = bn + wn0 + j * 8 + cc;
            *(float2*)(Cf + (size_t)row * HIDDEN + col) =
                make_float2(acc[i][j][0], acc[i][j][1]);
            *(float2*)(Cf + (size_t)(row + 8) * HIDDEN + col) =
                make_float2(acc[i][j][2], acc[i][j][3]);
        }
    }
}

// ---------------- flash attention, fp16 2-pass (base-2 softmax) -----------------
// QK: qh*kh + qh*kl.  PV: p*vh + p*vl (p plain fp16).  Output: bf16 hi/lo.
__global__ __launch_bounds__(256)
void attn_mma(const __half* __restrict__ Qh,
              const __half* __restrict__ Kh, const __half* __restrict__ Kl,
              const __half* __restrict__ Vh, const __half* __restrict__ Vl,
              __nv_bfloat16* __restrict__ AOh, __nv_bfloat16* __restrict__ AOl)
{
    extern __shared__ __align__(1024) char smem[];
    const uint32_t sb = smem_u32(smem);
    const int tid  = threadIdx.x;
    const int wid  = tid >> 5;
    const int lane = tid & 31;
    const int q0   = blockIdx.x * 128;
    const int h    = blockIdx.y;
    const int b    = blockIdx.z;

    const size_t hb = ((size_t)b * SEQ) * HIDDEN + (size_t)h * DK;
    const char* gqh = (const char*)(Qh + hb + (size_t)q0 * HIDDEN);
    const char* gkh = (const char*)(Kh + hb);
    const char* gkl = (const char*)(Kl + hb);
    const char* gvh = (const char*)(Vh + hb);
    const char* gvl = (const char*)(Vl + hb);

    auto load_tile = [&](uint32_t soff, const char* g) {
        #pragma unroll
        for (int r = 0; r < 8; r++) {
            int idx = r * 256 + tid;
            int row = idx >> 4, u = idx & 15;
            uint32_t sa = sb + soff + (uint32_t)(u >> 3) * 16384
                        + (uint32_t)row * 128
                        + (((uint32_t)(u & 7) * 16) ^ ((uint32_t)(row & 7) * 16));
            cp16(sa, g + (size_t)row * (HIDDEN * 2) + (size_t)u * 16);
        }
    };

    load_tile(A_SQH, gqh);
    load_tile(A_SKH, gkh);
    load_tile(A_SKL, gkl);
    CP_COMMIT();
    CP_WAIT(0);
    __syncthreads();

    float of[16][4] = {};
    float m0 = -INFINITY, m1 = -INFINITY, l0 = 0.f, l1 = 0.f;

    const uint32_t q_row = (uint32_t)(16 * wid + (lane & 15));
    const uint32_t q_kof = (uint32_t)(lane >> 4) * 16;
    const uint32_t q_xm  = (q_row & 7) * 16;
    const uint32_t q_rb  = q_row * 128;

    const uint32_t k_r   = (uint32_t)(((lane >> 4) & 1) * 8 + (lane & 7));
    const uint32_t k_kof = (uint32_t)((lane >> 3) & 1) * 16;

    const int v_grp  = lane >> 3;
    const uint32_t v_krow = (uint32_t)((v_grp & 1) * 8 + (lane & 7));
    const uint32_t v_ncol = (uint32_t)((v_grp >> 1) * 8);

    for (int t = 0; t < 16; t++) {
        load_tile(A_SVH, gvh + (size_t)t * 128 * (HIDDEN * 2));
        load_tile(A_SVL, gvl + (size_t)t * 128 * (HIDDEN * 2));
        CP_COMMIT();

        float sf[16][4] = {};
        #pragma unroll
        for (int ks = 0; ks < 8; ks++) {
            uint32_t qa = sb + A_SQH + (uint32_t)(ks >> 2) * 16384 + q_rb
                        + ((((uint32_t)(ks & 3) * 32) + q_kof) ^ q_xm);
            uint32_t qh4[4];
            ldsm_x4(qh4[0], qh4[1], qh4[2], qh4[3], qa);
            #pragma unroll
            for (int j16 = 0; j16 < 8; j16++) {
                uint32_t krow = (uint32_t)j16 * 16 + k_r;
                uint32_t ka = sb + A_SKH + (uint32_t)(ks >> 2) * 16384 + krow * 128
                            + ((((uint32_t)(ks & 3) * 32) + k_kof) ^ ((krow & 7) * 16));
                uint32_t kh4[4], kl4[4];
                ldsm_x4(kh4[0], kh4[1], kh4[2], kh4[3], ka);
                ldsm_x4(kl4[0], kl4[1], kl4[2], kl4[3], ka + (A_SKL - A_SKH));
                mma_f16(sf[2*j16],   qh4, kh4[0], kh4[1]);
                mma_f16(sf[2*j16+1], qh4, kh4[2], kh4[3]);
                mma_f16(sf[2*j16],   qh4, kl4[0], kl4[1]);
                mma_f16(sf[2*j16+1], qh4, kl4[2], kl4[3]);
            }
        }

        CP_WAIT(0);
        __syncthreads();

        if (t + 1 < 16) {
            load_tile(A_SKH, gkh + (size_t)(t + 1) * 128 * (HIDDEN * 2));
            load_tile(A_SKL, gkl + (size_t)(t + 1) * 128 * (HIDDEN * 2));
            CP_COMMIT();
        }

        // ---- online softmax, base 2 ----
        float tm0 = m0, tm1 = m1;
        #pragma unroll
        for (int f = 0; f < 16; f++) {
            tm0 = fmaxf(tm0, fmaxf(sf[f][0], sf[f][1]));
            tm1 = fmaxf(tm1, fmaxf(sf[f][2], sf[f][3]));
        }
        tm0 = fmaxf(tm0, __shfl_xor_sync(0xffffffff, tm0, 1));
        tm0 = fmaxf(tm0, __shfl_xor_sync(0xffffffff, tm0, 2));
        tm1 = fmaxf(tm1, __shfl_xor_sync(0xffffffff, tm1, 1));
        tm1 = fmaxf(tm1, __shfl_xor_sync(0xffffffff, tm1, 2));
        float cor0 = exp2f(m0 - tm0);
        float cor1 = exp2f(m1 - tm1);
        m0 = tm0; m1 = tm1;
        float s0 = 0.f, s1 = 0.f;
        #pragma unroll
        for (int f = 0; f < 16; f++) {
            sf[f][0] = exp2f(sf[f][0] - m0);
            sf[f][1] = exp2f(sf[f][1] - m0);
            sf[f][2] = exp2f(sf[f][2] - m1);
            sf[f][3] = exp2f(sf[f][3] - m1);
            s0 += sf[f][0] + sf[f][1];
            s1 += sf[f][2] + sf[f][3];
        }
        s0 += __shfl_xor_sync(0xffffffff, s0, 1);
        s0 += __shfl_xor_sync(0xffffffff, s0, 2);
        s1 += __shfl_xor_sync(0xffffffff, s1, 1);
        s1 += __shfl_xor_sync(0xffffffff, s1, 2);
        l0 = l0 * cor0 + s0;
        l1 = l1 * cor1 + s1;
        #pragma unroll
        for (int f = 0; f < 16; f++) {
            of[f][0] *= cor0; of[f][1] *= cor0;
            of[f][2] *= cor1; of[f][3] *= cor1;
        }

        // ---- O += P V (P plain fp16; V corrected via Vl) ----
        #pragma unroll
        for (int ks = 0; ks < 8; ks++) {
            uint32_t ph[4];
            ph[0] = pack2h(sf[2*ks][0],   sf[2*ks][1]);
            ph[1] = pack2h(sf[2*ks][2],   sf[2*ks][3]);
            ph[2] = pack2h(sf[2*ks+1][0], sf[2*ks+1][1]);
            ph[3] = pack2h(sf[2*ks+1][2], sf[2*ks+1][3]);
            uint32_t vkey = (uint32_t)ks * 16 + v_krow;
            #pragma unroll
            for (int j16 = 0; j16 < 8; j16++) {
                uint32_t ncol = (uint32_t)j16 * 16 + v_ncol;
                uint32_t va = sb + A_SVH + (ncol >> 6) * 16384 + vkey * 128
                            + (((ncol & 63) * 2) ^ ((vkey & 7) * 16));
                uint32_t vh4[4], vl4[4];
                ldsm_x4_t(vh4[0], vh4[1], vh4[2], vh4[3], va);
                ldsm_x4_t(vl4[0], vl4[1], vl4[2], vl4[3], va + (A_SVL - A_SVH));
                mma_f16(of[2*j16],   ph, vh4[0], vh4[1]);
                mma_f16(of[2*j16+1], ph, vh4[2], vh4[3]);
                mma_f16(of[2*j16],   ph, vl4[0], vl4[1]);
                mma_f16(of[2*j16+1], ph, vl4[2], vl4[3]);
            }
        }

        CP_WAIT(0);
        __syncthreads();
    }

    const float inv0 = 1.f / l0;
    const float inv1 = 1.f / l1;
    const int r0 = q0 + 16 * wid + (lane >> 2);
    const int cc = (lane & 3) * 2;
    #pragma unroll
    for (int f = 0; f < 16; f++) {
        int col = f * 8 + cc;
        uint32_t h0, lo0, h1, lo1;
        split2b(of[f][0] * inv0, of[f][1] * inv0, h0, lo0);
        split2b(of[f][2] * inv1, of[f][3] * inv1, h1, lo1);
        size_t o0 = hb + (size_t)r0 * HIDDEN + col;
        size_t o1 = hb + (size_t)(r0 + 8) * HIDDEN + col;
        *(uint32_t*)(AOh + o0) = h0;
        *(uint32_t*)(AOl + o0) = lo0;
        *(uint32_t*)(AOh + o1) = h1;
        *(uint32_t*)(AOl + o1) = lo1;
    }
}

// ------------------------------------------------------------------------------
extern "C" void kernel_launch(void* const* d_in, const int* in_sizes, int n_in,
                              void* d_out, int out_size)
{
    const float* x  = (const float*)d_in[0];
    const float* wq = (const float*)d_in[1];
    const float* wk = (const float*)d_in[2];
    const float* wv = (const float*)d_in[3];
    const float* wo = (const float*)d_in[4];
    float* out = (float*)d_out;

    __half *qh, *ql, *kh, *kl, *vh, *vl, *xh, *xl, *wqh, *wkh, *wvh;
    __nv_bfloat16 *aoh, *aol, *woh, *wol;
    cudaGetSymbolAddress((void**)&qh,  g_qh);  cudaGetSymbolAddress((void**)&ql,  g_ql);
    cudaGetSymbolAddress((void**)&kh,  g_kh);  cudaGetSymbolAddress((void**)&kl,  g_kl);
    cudaGetSymbolAddress((void**)&vh,  g_vh);  cudaGetSymbolAddress((void**)&vl,  g_vl);
    cudaGetSymbolAddress((void**)&xh,  g_xh);  cudaGetSymbolAddress((void**)&xl,  g_xl);
    cudaGetSymbolAddress((void**)&wqh, g_wqh);
    cudaGetSymbolAddress((void**)&wkh, g_wkh);
    cudaGetSymbolAddress((void**)&wvh, g_wvh);
    cudaGetSymbolAddress((void**)&aoh, g_aoh); cudaGetSymbolAddress((void**)&aol, g_aol);
    cudaGetSymbolAddress((void**)&woh, g_woh); cudaGetSymbolAddress((void**)&wol, g_wol);

    cudaFuncSetAttribute(gemm_f16_2p, cudaFuncAttributeMaxDynamicSharedMemorySize,
                         SMEM_G2);
    cudaFuncSetAttribute(gemm_bf16_3p, cudaFuncAttributeMaxDynamicSharedMemorySize,
                         SMEM_G3);
    cudaFuncSetAttribute(attn_mma, cudaFuncAttributeMaxDynamicSharedMemorySize,
                         SMEM_ATTN);

    // fused convert: x,wq,wk,wv -> fp16 hi/lo; wo -> bf16 hi/lo.
    // (w lo outputs for q/k/v are written into the matching q/k/v lo scratch
    //  then overwritten by the projection epilogues before any use — but to be
    //  safe, route them into unique unused halves: reuse ql/kl/vl is NOT safe.
    //  Instead write w-lo into xl's twin buffers: use g_ql/g_kl/g_vl BEFORE the
    //  GEMM that overwrites them — ordering is safe since cvt completes first.)
    dim3 gcvt((HIDDEN * HIDDEN) / 4 / 256, 5);   // (16384, 5)
    cvt5<<<gcvt, 256>>>(
        (const float4*)x,  (uint32_t*)xh,  (uint32_t*)xl,
        (const float4*)wq, (uint32_t*)wqh, (uint32_t*)ql,
        (const float4*)wk, (uint32_t*)wkh, (uint32_t*)kl,
        (const float4*)wv, (uint32_t*)wvh, (uint32_t*)vl,
        (const float4*)wo, (uint32_t*)woh, (uint32_t*)wol);

    // fused Q/K/V projections (fp16 2-pass); Q pre-scaled for base-2 softmax
    dim3 gqkv(HIDDEN / NT, MTOK / MT, 3);   // (32, 64, 3)
    gemm_f16_2p<<<gqkv, 256, SMEM_G2>>>(
        xh, xl, wqh, wkh, wvh,
        qh, ql, kh, kl, vh, vl, QSCALE2);

    dim3 ga(SEQ / 128, NHEADS, BATCH);      // (16, 32, 2)
    attn_mma<<<ga, 256, SMEM_ATTN>>>(qh, kh, kl, vh, vl, aoh, aol);

    // output projection: bf16 3-pass, fp32 result
    dim3 go(HIDDEN / NT, MTOK / MT);        // (32, 64)
    gemm_bf16_3p<<<go, 256, SMEM_G3>>>(aoh, aol, woh, wol, out);
}

// round 16
// speedup vs baseline: 1.5363x; 1.1399x over previous
#include <cuda_runtime.h>
#include <cuda_bf16.h>
#include <cuda_fp16.h>
#include <math.h>
#include <stdint.h>

#define HIDDEN 4096
#define NHEADS 32
#define DK     128
#define BATCH  2
#define SEQ    2048
#define MTOK   (BATCH*SEQ)   // 4096

// GEMM tiling: 64x128 CTA tile, 2-stage, 2 CTAs/SM
#define MT 64
#define NT 128
#define NCHUNK (HIDDEN / 64)   // 64
#define ST_A 8192              // 64 rows x 128B

// fp16 2-pass stage: Ah, Al, Bh -> 32KB
#define STG2 (2*ST_A + 16384)
#define SMEM_G2 (2 * STG2)                    // 65536

// attention smem (fp16): Qh, Kh, Kl, Vh (32KB each)
#define A_SQH 0
#define A_SKH 32768
#define A_SKL 65536
#define A_SVH 98304
#define SMEM_ATTN 131072

// Q epilogue scale: (1/sqrt(128)) * log2(e)  -> softmax runs in base 2
#define QSCALE2 0.12754239511348782f

// ---------------- scratch ----------------------------------------------------
__device__ __half g_qh [MTOK * HIDDEN];
__device__ __half g_ql [MTOK * HIDDEN];
__device__ __half g_kh [MTOK * HIDDEN];
__device__ __half g_kl [MTOK * HIDDEN];
__device__ __half g_vh [MTOK * HIDDEN];
__device__ __half g_vl [MTOK * HIDDEN];
__device__ __half g_xh [MTOK * HIDDEN];
__device__ __half g_xl [MTOK * HIDDEN];
__device__ __half g_aoh[MTOK * HIDDEN];
__device__ __half g_aol[MTOK * HIDDEN];
__device__ __half g_wqh[HIDDEN * HIDDEN];
__device__ __half g_wkh[HIDDEN * HIDDEN];
__device__ __half g_wvh[HIDDEN * HIDDEN];
__device__ __half g_woh[HIDDEN * HIDDEN];
__device__ __half g_wol[HIDDEN * HIDDEN];   // written by cvt, never read

// ---------------- PTX helpers -------------------------------------------------
__device__ __forceinline__ uint32_t smem_u32(const void* p) {
    uint32_t a;
    asm("{ .reg .u64 t; cvta.to.shared.u64 t, %1; cvt.u32.u64 %0, t; }"
        : "=r"(a) : "l"(p));
    return a;
}
__device__ __forceinline__ void cp16(uint32_t dst, const void* src) {
    asm volatile("cp.async.cg.shared.global [%0], [%1], 16;"
                 :: "r"(dst), "l"(src) : "memory");
}
#define CP_COMMIT() asm volatile("cp.async.commit_group;" ::: "memory")
#define CP_WAIT(n)  asm volatile("cp.async.wait_group %0;" :: "n"(n) : "memory")

__device__ __forceinline__ void ldsm_x4(uint32_t& r0, uint32_t& r1,
                                        uint32_t& r2, uint32_t& r3, uint32_t a) {
    asm volatile("ldmatrix.sync.aligned.m8n8.x4.shared.b16 {%0,%1,%2,%3}, [%4];"
                 : "=r"(r0), "=r"(r1), "=r"(r2), "=r"(r3) : "r"(a));
}
__device__ __forceinline__ void ldsm_x4_t(uint32_t& r0, uint32_t& r1,
                                          uint32_t& r2, uint32_t& r3, uint32_t a) {
    asm volatile("ldmatrix.sync.aligned.m8n8.x4.trans.shared.b16 {%0,%1,%2,%3}, [%4];"
                 : "=r"(r0), "=r"(r1), "=r"(r2), "=r"(r3) : "r"(a));
}
__device__ __forceinline__ void mma_f16(float* c, const uint32_t* a,
                                        uint32_t b0, uint32_t b1) {
    asm volatile(
        "mma.sync.aligned.m16n8k16.row.col.f32.f16.f16.f32 "
        "{%0,%1,%2,%3}, {%4,%5,%6,%7}, {%8,%9}, {%0,%1,%2,%3};"
        : "+f"(c[0]), "+f"(c[1]), "+f"(c[2]), "+f"(c[3])
        : "r"(a[0]), "r"(a[1]), "r"(a[2]), "r"(a[3]), "r"(b0), "r"(b1));
}
__device__ __forceinline__ void split2h(float a, float b, uint32_t& hi, uint32_t& lo) {
    __half ha = __float2half_rn(a), hb = __float2half_rn(b);
    __half la = __float2half_rn(a - __half2float(ha));
    __half lb = __float2half_rn(b - __half2float(hb));
    __half2 H = __halves2half2(ha, hb), L = __halves2half2(la, lb);
    hi = *(uint32_t*)&H; lo = *(uint32_t*)&L;
}
__device__ __forceinline__ uint32_t pack2h(float a, float b) {
    __half2 t = __floats2half2_rn(a, b);
    return *(uint32_t*)&t;
}

// ---------------- fused fp32 -> fp16 hi/lo split (5 tensors, one launch) -------
__global__ __launch_bounds__(256)
void cvt5(const float4* __restrict__ s0, uint32_t* __restrict__ h0, uint32_t* __restrict__ l0,
          const float4* __restrict__ s1, uint32_t* __restrict__ h1, uint32_t* __restrict__ l1,
          const float4* __restrict__ s2, uint32_t* __restrict__ h2, uint32_t* __restrict__ l2,
          const float4* __restrict__ s3, uint32_t* __restrict__ h3, uint32_t* __restrict__ l3,
          const float4* __restrict__ s4, uint32_t* __restrict__ h4, uint32_t* __restrict__ l4)
{
    const int t = blockIdx.y;
    const float4* s = (t == 0) ? s0 : (t == 1) ? s1 : (t == 2) ? s2 : (t == 3) ? s3 : s4;
    uint32_t* h = (t == 0) ? h0 : (t == 1) ? h1 : (t == 2) ? h2 : (t == 3) ? h3 : h4;
    uint32_t* l = (t == 0) ? l0 : (t == 1) ? l1 : (t == 2) ? l2 : (t == 3) ? l3 : l4;

    size_t i = (size_t)blockIdx.x * 256 + threadIdx.x;
    float4 v = s[i];
    uint32_t a0, b0, a1, b1;
    split2h(v.x, v.y, a0, b0);
    split2h(v.z, v.w, a1, b1);
    h[2*i]   = a0;
    h[2*i+1] = a1;
    l[2*i]   = b0;
    l[2*i+1] = b1;
}

// ---------------- fp16 2-pass GEMM: C = (Ah+Al) @ Bh^T --------------------------
// z selects B/C set (fused QKV). If Cf != nullptr: fp32 output (use gridDim.z=1).
__global__ __launch_bounds__(256, 2)
void gemm_f16_2p(const __half* __restrict__ Ah, const __half* __restrict__ Al,
                 const __half* __restrict__ B0h, const __half* __restrict__ B1h,
                 const __half* __restrict__ B2h,
                 __half* __restrict__ C0h, __half* __restrict__ C0l,
                 __half* __restrict__ C1h, __half* __restrict__ C1l,
                 __half* __restrict__ C2h, __half* __restrict__ C2l,
                 float* __restrict__ Cf, float scale0)
{
    extern __shared__ __align__(1024) char smem[];
    const uint32_t sb = smem_u32(smem);
    const int tid  = threadIdx.x;
    const int wid  = tid >> 5;
    const int lane = tid & 31;
    const int bm   = blockIdx.y * MT;
    const int bn   = blockIdx.x * NT;
    const int z    = blockIdx.z;

    const __half* Bh = (z == 0) ? B0h : (z == 1) ? B1h : B2h;
    __half* Ch = (z == 0) ? C0h : (z == 1) ? C1h : C2h;
    __half* Cl = (z == 0) ? C0l : (z == 1) ? C1l : C2l;
    const float scale = (z == 0) ? scale0 : 1.0f;

    const int wm0 = (wid & 1) * 32;
    const int wn0 = (wid >> 1) * 32;

    const char* gah = (const char*)Ah + (size_t)bm * (HIDDEN * 2);
    const char* gal = (const char*)Al + (size_t)bm * (HIDDEN * 2);
    const char* gbh = (const char*)Bh + (size_t)bn * (HIDDEN * 2);

    const int a_r = lane & 15;
    const uint32_t a_k16 = (lane >> 4) * 16;
    uint32_t a_rb[2], a_xm[2];
    #pragma unroll
    for (int i = 0; i < 2; i++) {
        int row = wm0 + i * 16 + a_r;
        a_rb[i] = (uint32_t)row * 128;
        a_xm[i] = (uint32_t)(row & 7) * 16;
    }
    const int b_r = ((lane >> 4) & 1) * 8 + (lane & 7);
    const uint32_t b_k16 = ((lane >> 3) & 1) * 16;
    uint32_t b_rb[2], b_xm[2];
    #pragma unroll
    for (int j = 0; j < 2; j++) {
        int row = wn0 + j * 16 + b_r;
        b_rb[j] = (uint32_t)row * 128;
        b_xm[j] = (uint32_t)(row & 7) * 16;
    }

    float acc[2][4][4] = {};

    auto load_stage = [&](int s, int c) {
        const uint32_t st = sb + (uint32_t)s * STG2;
        const size_t cb = (size_t)c * 128;
        #pragma unroll
        for (int u = 0; u < 2; u++) {
            int idx = u * 256 + tid;
            uint32_t bo = (uint32_t)idx << 4;
            uint32_t sw = bo ^ ((bo >> 3) & 0x70);
            size_t go = (size_t)(idx >> 3) * (HIDDEN * 2) + (size_t)(idx & 7) * 16 + cb;
            cp16(st + sw, gah + go);
            cp16(st + ST_A + sw, gal + go);
        }
        #pragma unroll
        for (int u = 0; u < 4; u++) {
            int idx = u * 256 + tid;
            uint32_t bo = (uint32_t)idx << 4;
            uint32_t sw = bo ^ ((bo >> 3) & 0x70);
            size_t go = (size_t)(idx >> 3) * (HIDDEN * 2) + (size_t)(idx & 7) * 16 + cb;
            cp16(st + 2 * ST_A + sw, gbh + go);
        }
        CP_COMMIT();
    };

    load_stage(0, 0);

    for (int c = 0; c < NCHUNK; c++) {
        CP_WAIT(0);
        __syncthreads();
        if (c + 1 < NCHUNK) load_stage((c + 1) & 1, c + 1);

        const uint32_t st  = sb + (uint32_t)(c & 1) * STG2;
        const uint32_t tAh = st;
        const uint32_t tAl = st + ST_A;
        const uint32_t tBh = st + 2 * ST_A;

        #pragma unroll
        for (int ks = 0; ks < 4; ks++) {
            const uint32_t ak = (uint32_t)ks * 32 + a_k16;
            const uint32_t bk = (uint32_t)ks * 32 + b_k16;

            uint32_t ah[2][4], al[2][4], bh[2][4];
            #pragma unroll
            for (int i = 0; i < 2; i++) {
                uint32_t off = a_rb[i] + (ak ^ a_xm[i]);
                ldsm_x4(ah[i][0], ah[i][1], ah[i][2], ah[i][3], tAh + off);
                ldsm_x4(al[i][0], al[i][1], al[i][2], al[i][3], tAl + off);
            }
            #pragma unroll
            for (int j = 0; j < 2; j++) {
                uint32_t off = b_rb[j] + (bk ^ b_xm[j]);
                ldsm_x4(bh[j][0], bh[j][1], bh[j][2], bh[j][3], tBh + off);
            }
            #pragma unroll
            for (int i = 0; i < 2; i++)
                #pragma unroll
                for (int j = 0; j < 4; j++)
                    mma_f16(acc[i][j], ah[i],
                            bh[j >> 1][(j & 1) * 2], bh[j >> 1][(j & 1) * 2 + 1]);
            #pragma unroll
            for (int i = 0; i < 2; i++)
                #pragma unroll
                for (int j = 0; j < 4; j++)
                    mma_f16(acc[i][j], al[i],
                            bh[j >> 1][(j & 1) * 2], bh[j >> 1][(j & 1) * 2 + 1]);
        }
    }

    const int cr = lane >> 2;
    const int cc = (lane & 3) * 2;
    #pragma unroll
    for (int i = 0; i < 2; i++) {
        #pragma unroll
        for (int j = 0; j < 4; j++) {
            int row = bm + wm0 + i * 16 + cr;
            int col = bn + wn0 + j * 8 + cc;
            if (Cf) {
                *(float2*)(Cf + (size_t)row * HIDDEN + col) =
                    make_float2(acc[i][j][0], acc[i][j][1]);
                *(float2*)(Cf + (size_t)(row + 8) * HIDDEN + col) =
                    make_float2(acc[i][j][2], acc[i][j][3]);
            } else {
                uint32_t h0, l0, h1, l1;
                split2h(acc[i][j][0] * scale, acc[i][j][1] * scale, h0, l0);
                split2h(acc[i][j][2] * scale, acc[i][j][3] * scale, h1, l1);
                *(uint32_t*)(Ch + (size_t)row * HIDDEN + col)       = h0;
                *(uint32_t*)(Cl + (size_t)row * HIDDEN + col)       = l0;
                *(uint32_t*)(Ch + (size_t)(row + 8) * HIDDEN + col) = h1;
                *(uint32_t*)(Cl + (size_t)(row + 8) * HIDDEN + col) = l1;
            }
        }
    }
}

// ---------------- flash attention, fp16 (base-2 softmax) ------------------------
// QK: qh*kh + qh*kl (2-pass). PV: p*vh (single pass; P plain fp16).
// Output: fp16 hi/lo for the 2-pass O projection.
__global__ __launch_bounds__(256)
void attn_mma(const __half* __restrict__ Qh,
              const __half* __restrict__ Kh, const __half* __restrict__ Kl,
              const __half* __restrict__ Vh,
              __half* __restrict__ AOh, __half* __restrict__ AOl)
{
    extern __shared__ __align__(1024) char smem[];
    const uint32_t sb = smem_u32(smem);
    const int tid  = threadIdx.x;
    const int wid  = tid >> 5;
    const int lane = tid & 31;
    const int q0   = blockIdx.x * 128;
    const int h    = blockIdx.y;
    const int b    = blockIdx.z;

    const size_t hb = ((size_t)b * SEQ) * HIDDEN + (size_t)h * DK;
    const char* gqh = (const char*)(Qh + hb + (size_t)q0 * HIDDEN);
    const char* gkh = (const char*)(Kh + hb);
    const char* gkl = (const char*)(Kl + hb);
    const char* gvh = (const char*)(Vh + hb);

    auto load_tile = [&](uint32_t soff, const char* g) {
        #pragma unroll
        for (int r = 0; r < 8; r++) {
            int idx = r * 256 + tid;
            int row = idx >> 4, u = idx & 15;
            uint32_t sa = sb + soff + (uint32_t)(u >> 3) * 16384
                        + (uint32_t)row * 128
                        + (((uint32_t)(u & 7) * 16) ^ ((uint32_t)(row & 7) * 16));
            cp16(sa, g + (size_t)row * (HIDDEN * 2) + (size_t)u * 16);
        }
    };

    load_tile(A_SQH, gqh);
    load_tile(A_SKH, gkh);
    load_tile(A_SKL, gkl);
    CP_COMMIT();
    CP_WAIT(0);
    __syncthreads();

    float of[16][4] = {};
    float m0 = -INFINITY, m1 = -INFINITY, l0 = 0.f, l1 = 0.f;

    const uint32_t q_row = (uint32_t)(16 * wid + (lane & 15));
    const uint32_t q_kof = (uint32_t)(lane >> 4) * 16;
    const uint32_t q_xm  = (q_row & 7) * 16;
    const uint32_t q_rb  = q_row * 128;

    const uint32_t k_r   = (uint32_t)(((lane >> 4) & 1) * 8 + (lane & 7));
    const uint32_t k_kof = (uint32_t)((lane >> 3) & 1) * 16;

    const int v_grp  = lane >> 3;
    const uint32_t v_krow = (uint32_t)((v_grp & 1) * 8 + (lane & 7));
    const uint32_t v_ncol = (uint32_t)((v_grp >> 1) * 8);

    for (int t = 0; t < 16; t++) {
        load_tile(A_SVH, gvh + (size_t)t * 128 * (HIDDEN * 2));
        CP_COMMIT();

        float sf[16][4] = {};
        #pragma unroll
        for (int ks = 0; ks < 8; ks++) {
            uint32_t qa = sb + A_SQH + (uint32_t)(ks >> 2) * 16384 + q_rb
                        + ((((uint32_t)(ks & 3) * 32) + q_kof) ^ q_xm);
            uint32_t qh4[4];
            ldsm_x4(qh4[0], qh4[1], qh4[2], qh4[3], qa);
            #pragma unroll
            for (int j16 = 0; j16 < 8; j16++) {
                uint32_t krow = (uint32_t)j16 * 16 + k_r;
                uint32_t ka = sb + A_SKH + (uint32_t)(ks >> 2) * 16384 + krow * 128
                            + ((((uint32_t)(ks & 3) * 32) + k_kof) ^ ((krow & 7) * 16));
                uint32_t kh4[4], kl4[4];
                ldsm_x4(kh4[0], kh4[1], kh4[2], kh4[3], ka);
                ldsm_x4(kl4[0], kl4[1], kl4[2], kl4[3], ka + (A_SKL - A_SKH));
                mma_f16(sf[2*j16],   qh4, kh4[0], kh4[1]);
                mma_f16(sf[2*j16+1], qh4, kh4[2], kh4[3]);
                mma_f16(sf[2*j16],   qh4, kl4[0], kl4[1]);
                mma_f16(sf[2*j16+1], qh4, kl4[2], kl4[3]);
            }
        }

        CP_WAIT(0);
        __syncthreads();

        if (t + 1 < 16) {
            load_tile(A_SKH, gkh + (size_t)(t + 1) * 128 * (HIDDEN * 2));
            load_tile(A_SKL, gkl + (size_t)(t + 1) * 128 * (HIDDEN * 2));
            CP_COMMIT();
        }

        // ---- online softmax, base 2 ----
        float tm0 = m0, tm1 = m1;
        #pragma unroll
        for (int f = 0; f < 16; f++) {
            tm0 = fmaxf(tm0, fmaxf(sf[f][0], sf[f][1]));
            tm1 = fmaxf(tm1, fmaxf(sf[f][2], sf[f][3]));
        }
        tm0 = fmaxf(tm0, __shfl_xor_sync(0xffffffff, tm0, 1));
        tm0 = fmaxf(tm0, __shfl_xor_sync(0xffffffff, tm0, 2));
        tm1 = fmaxf(tm1, __shfl_xor_sync(0xffffffff, tm1, 1));
        tm1 = fmaxf(tm1, __shfl_xor_sync(0xffffffff, tm1, 2));
        float cor0 = exp2f(m0 - tm0);
        float cor1 = exp2f(m1 - tm1);
        m0 = tm0; m1 = tm1;
        float s0 = 0.f, s1 = 0.f;
        #pragma unroll
        for (int f = 0; f < 16; f++) {
            sf[f][0] = exp2f(sf[f][0] - m0);
            sf[f][1] = exp2f(sf[f][1] - m0);
            sf[f][2] = exp2f(sf[f][2] - m1);
            sf[f][3] = exp2f(sf[f][3] - m1);
            s0 += sf[f][0] + sf[f][1];
            s1 += sf[f][2] + sf[f][3];
        }
        s0 += __shfl_xor_sync(0xffffffff, s0, 1);
        s0 += __shfl_xor_sync(0xffffffff, s0, 2);
        s1 += __shfl_xor_sync(0xffffffff, s1, 1);
        s1 += __shfl_xor_sync(0xffffffff, s1, 2);
        l0 = l0 * cor0 + s0;
        l1 = l1 * cor1 + s1;
        #pragma unroll
        for (int f = 0; f < 16; f++) {
            of[f][0] *= cor0; of[f][1] *= cor0;
            of[f][2] *= cor1; of[f][3] *= cor1;
        }

        // ---- O += P Vh (single pass) ----
        #pragma unroll
        for (int ks = 0; ks < 8; ks++) {
            uint32_t ph[4];
            ph[0] = pack2h(sf[2*ks][0],   sf[2*ks][1]);
            ph[1] = pack2h(sf[2*ks][2],   sf[2*ks][3]);
            ph[2] = pack2h(sf[2*ks+1][0], sf[2*ks+1][1]);
            ph[3] = pack2h(sf[2*ks+1][2], sf[2*ks+1][3]);
            uint32_t vkey = (uint32_t)ks * 16 + v_krow;
            #pragma unroll
            for (int j16 = 0; j16 < 8; j16++) {
                uint32_t ncol = (uint32_t)j16 * 16 + v_ncol;
                uint32_t va = sb + A_SVH + (ncol >> 6) * 16384 + vkey * 128
                            + (((ncol & 63) * 2) ^ ((vkey & 7) * 16));
                uint32_t vh4[4];
                ldsm_x4_t(vh4[0], vh4[1], vh4[2], vh4[3], va);
                mma_f16(of[2*j16],   ph, vh4[0], vh4[1]);
                mma_f16(of[2*j16+1], ph, vh4[2], vh4[3]);
            }
        }

        CP_WAIT(0);
        __syncthreads();
    }

    const float inv0 = 1.f / l0;
    const float inv1 = 1.f / l1;
    const int r0 = q0 + 16 * wid + (lane >> 2);
    const int cc = (lane & 3) * 2;
    #pragma unroll
    for (int f = 0; f < 16; f++) {
        int col = f * 8 + cc;
        uint32_t h0, lo0, h1, lo1;
        split2h(of[f][0] * inv0, of[f][1] * inv0, h0, lo0);
        split2h(of[f][2] * inv1, of[f][3] * inv1, h1, lo1);
        size_t o0 = hb + (size_t)r0 * HIDDEN + col;
        size_t o1 = hb + (size_t)(r0 + 8) * HIDDEN + col;
        *(uint32_t*)(AOh + o0) = h0;
        *(uint32_t*)(AOl + o0) = lo0;
        *(uint32_t*)(AOh + o1) = h1;
        *(uint32_t*)(AOl + o1) = lo1;
    }
}

// ------------------------------------------------------------------------------
extern "C" void kernel_launch(void* const* d_in, const int* in_sizes, int n_in,
                              void* d_out, int out_size)
{
    const float* x  = (const float*)d_in[0];
    const float* wq = (const float*)d_in[1];
    const float* wk = (const float*)d_in[2];
    const float* wv = (const float*)d_in[3];
    const float* wo = (const float*)d_in[4];
    float* out = (float*)d_out;

    __half *qh, *ql, *kh, *kl, *vh, *vl, *xh, *xl, *aoh, *aol;
    __half *wqh, *wkh, *wvh, *woh, *wol;
    cudaGetSymbolAddress((void**)&qh,  g_qh);  cudaGetSymbolAddress((void**)&ql,  g_ql);
    cudaGetSymbolAddress((void**)&kh,  g_kh);  cudaGetSymbolAddress((void**)&kl,  g_kl);
    cudaGetSymbolAddress((void**)&vh,  g_vh);  cudaGetSymbolAddress((void**)&vl,  g_vl);
    cudaGetSymbolAddress((void**)&xh,  g_xh);  cudaGetSymbolAddress((void**)&xl,  g_xl);
    cudaGetSymbolAddress((void**)&aoh, g_aoh); cudaGetSymbolAddress((void**)&aol, g_aol);
    cudaGetSymbolAddress((void**)&wqh, g_wqh);
    cudaGetSymbolAddress((void**)&wkh, g_wkh);
    cudaGetSymbolAddress((void**)&wvh, g_wvh);
    cudaGetSymbolAddress((void**)&woh, g_woh);
    cudaGetSymbolAddress((void**)&wol, g_wol);

    cudaFuncSetAttribute(gemm_f16_2p, cudaFuncAttributeMaxDynamicSharedMemorySize,
                         SMEM_G2);
    cudaFuncSetAttribute(attn_mma, cudaFuncAttributeMaxDynamicSharedMemorySize,
                         SMEM_ATTN);

    // fused convert: all 5 tensors -> fp16 hi/lo (w lo halves parked in q/k/v lo
    // scratch, consumed only as cvt outputs before the projections overwrite them;
    // wo lo -> g_wol, unused)
    dim3 gcvt((HIDDEN * HIDDEN) / 4 / 256, 5);   // (16384, 5)
    cvt5<<<gcvt, 256>>>(
        (const float4*)x,  (uint32_t*)xh,  (uint32_t*)xl,
        (const float4*)wq, (uint32_t*)wqh, (uint32_t*)ql,
        (const float4*)wk, (uint32_t*)wkh, (uint32_t*)kl,
        (const float4*)wv, (uint32_t*)wvh, (uint32_t*)vl,
        (const float4*)wo, (uint32_t*)woh, (uint32_t*)wol);

    // fused Q/K/V projections (fp16 2-pass); Q pre-scaled for base-2 softmax
    dim3 gqkv(HIDDEN / NT, MTOK / MT, 3);   // (32, 64, 3)
    gemm_f16_2p<<<gqkv, 256, SMEM_G2>>>(
        xh, xl, wqh, wkh, wvh,
        qh, ql, kh, kl, vh, vl, nullptr, QSCALE2);

    dim3 ga(SEQ / 128, NHEADS, BATCH);      // (16, 32, 2)
    attn_mma<<<ga, 256, SMEM_ATTN>>>(qh, kh, kl, vh, aoh, aol);

    // output projection: fp16 2-pass, fp32 result
    dim3 go(HIDDEN / NT, MTOK / MT, 1);     // (32, 64, 1)
    gemm_f16_2p<<<go, 256, SMEM_G2>>>(
        aoh, aol, woh, woh, woh,
        nullptr, nullptr, nullptr, nullptr, nullptr, nullptr, out, 1.0f);
}

// round 17
// speedup vs baseline: 1.8089x; 1.1774x over previous
#include <cuda_runtime.h>
#include <cuda_fp16.h>
#include <math.h>
#include <stdint.h>

#define HIDDEN 4096
#define NHEADS 32
#define DK     128
#define BATCH  2
#define SEQ    2048
#define MTOK   (BATCH*SEQ)   // 4096

// GEMM tiling: 64x128 CTA tile, 2-stage, 2 CTAs/SM
#define MT 64
#define NT 128
#define NCHUNK (HIDDEN / 64)   // 64
#define ST_A 8192              // 64 rows x 128B

// stage: Ah, Al, Bh -> 32KB
#define STG2 (2*ST_A + 16384)
#define SMEM_G2 (2 * STG2)                    // 65536

// attention smem (fp16): Qh, Kh, Kl, Vh (32KB each)
#define A_SQH 0
#define A_SKH 32768
#define A_SKL 65536
#define A_SVH 98304
#define SMEM_ATTN 131072

// Q epilogue scale: (1/sqrt(128)) * log2(e)  -> softmax runs in base 2
#define QSCALE2 0.12754239511348782f

// ---------------- scratch ----------------------------------------------------
__device__ __half g_qh [MTOK * HIDDEN];
__device__ __half g_ql [MTOK * HIDDEN];
__device__ __half g_kh [MTOK * HIDDEN];
__device__ __half g_kl [MTOK * HIDDEN];
__device__ __half g_vh [MTOK * HIDDEN];
__device__ __half g_vl [MTOK * HIDDEN];   // parks wv_lo from cvt (unused by GEMM)
__device__ __half g_xh [MTOK * HIDDEN];
__device__ __half g_xl [MTOK * HIDDEN];
__device__ __half g_aoh[MTOK * HIDDEN];
__device__ __half g_wqh[HIDDEN * HIDDEN];
__device__ __half g_wkh[HIDDEN * HIDDEN];
__device__ __half g_wvh[HIDDEN * HIDDEN];
__device__ __half g_woh[HIDDEN * HIDDEN];
__device__ __half g_wol[HIDDEN * HIDDEN];   // written by cvt, never read

// ---------------- PTX helpers -------------------------------------------------
__device__ __forceinline__ uint32_t smem_u32(const void* p) {
    uint32_t a;
    asm("{ .reg .u64 t; cvta.to.shared.u64 t, %1; cvt.u32.u64 %0, t; }"
        : "=r"(a) : "l"(p));
    return a;
}
__device__ __forceinline__ void cp16(uint32_t dst, const void* src) {
    asm volatile("cp.async.cg.shared.global [%0], [%1], 16;"
                 :: "r"(dst), "l"(src) : "memory");
}
#define CP_COMMIT() asm volatile("cp.async.commit_group;" ::: "memory")
#define CP_WAIT(n)  asm volatile("cp.async.wait_group %0;" :: "n"(n) : "memory")

__device__ __forceinline__ void ldsm_x4(uint32_t& r0, uint32_t& r1,
                                        uint32_t& r2, uint32_t& r3, uint32_t a) {
    asm volatile("ldmatrix.sync.aligned.m8n8.x4.shared.b16 {%0,%1,%2,%3}, [%4];"
                 : "=r"(r0), "=r"(r1), "=r"(r2), "=r"(r3) : "r"(a));
}
__device__ __forceinline__ void ldsm_x4_t(uint32_t& r0, uint32_t& r1,
                                          uint32_t& r2, uint32_t& r3, uint32_t a) {
    asm volatile("ldmatrix.sync.aligned.m8n8.x4.trans.shared.b16 {%0,%1,%2,%3}, [%4];"
                 : "=r"(r0), "=r"(r1), "=r"(r2), "=r"(r3) : "r"(a));
}
__device__ __forceinline__ void mma_f16(float* c, const uint32_t* a,
                                        uint32_t b0, uint32_t b1) {
    asm volatile(
        "mma.sync.aligned.m16n8k16.row.col.f32.f16.f16.f32 "
        "{%0,%1,%2,%3}, {%4,%5,%6,%7}, {%8,%9}, {%0,%1,%2,%3};"
        : "+f"(c[0]), "+f"(c[1]), "+f"(c[2]), "+f"(c[3])
        : "r"(a[0]), "r"(a[1]), "r"(a[2]), "r"(a[3]), "r"(b0), "r"(b1));
}
__device__ __forceinline__ void split2h(float a, float b, uint32_t& hi, uint32_t& lo) {
    __half ha = __float2half_rn(a), hb = __float2half_rn(b);
    __half la = __float2half_rn(a - __half2float(ha));
    __half lb = __float2half_rn(b - __half2float(hb));
    __half2 H = __halves2half2(ha, hb), L = __halves2half2(la, lb);
    hi = *(uint32_t*)&H; lo = *(uint32_t*)&L;
}
__device__ __forceinline__ uint32_t pack2h(float a, float b) {
    __half2 t = __floats2half2_rn(a, b);
    return *(uint32_t*)&t;
}

// ---------------- fused fp32 -> fp16 hi/lo split (5 tensors, one launch) -------
__global__ __launch_bounds__(256)
void cvt5(const float4* __restrict__ s0, uint32_t* __restrict__ h0, uint32_t* __restrict__ l0,
          const float4* __restrict__ s1, uint32_t* __restrict__ h1, uint32_t* __restrict__ l1,
          const float4* __restrict__ s2, uint32_t* __restrict__ h2, uint32_t* __restrict__ l2,
          const float4* __restrict__ s3, uint32_t* __restrict__ h3, uint32_t* __restrict__ l3,
          const float4* __restrict__ s4, uint32_t* __restrict__ h4, uint32_t* __restrict__ l4)
{
    const int t = blockIdx.y;
    const float4* s = (t == 0) ? s0 : (t == 1) ? s1 : (t == 2) ? s2 : (t == 3) ? s3 : s4;
    uint32_t* h = (t == 0) ? h0 : (t == 1) ? h1 : (t == 2) ? h2 : (t == 3) ? h3 : h4;
    uint32_t* l = (t == 0) ? l0 : (t == 1) ? l1 : (t == 2) ? l2 : (t == 3) ? l3 : l4;

    size_t i = (size_t)blockIdx.x * 256 + threadIdx.x;
    float4 v = s[i];
    uint32_t a0, b0, a1, b1;
    split2h(v.x, v.y, a0, b0);
    split2h(v.z, v.w, a1, b1);
    h[2*i]   = a0;
    h[2*i+1] = a1;
    l[2*i]   = b0;
    l[2*i+1] = b1;
}

// ---------------- fp16 GEMM: C = (Ah [+ Al]) @ Bh^T -----------------------------
// z selects B/C set. Al pass executed iff bit z of lo_mask is set.
// If Cf != nullptr: fp32 output (use gridDim.z = 1).
__global__ __launch_bounds__(256, 2)
void gemm_f16(const __half* __restrict__ Ah, const __half* __restrict__ Al,
              const __half* __restrict__ B0h, const __half* __restrict__ B1h,
              const __half* __restrict__ B2h,
              __half* __restrict__ C0h, __half* __restrict__ C0l,
              __half* __restrict__ C1h, __half* __restrict__ C1l,
              __half* __restrict__ C2h, __half* __restrict__ C2l,
              float* __restrict__ Cf, float scale0, uint32_t lo_mask)
{
    extern __shared__ __align__(1024) char smem[];
    const uint32_t sb = smem_u32(smem);
    const int tid  = threadIdx.x;
    const int wid  = tid >> 5;
    const int lane = tid & 31;
    const int bm   = blockIdx.y * MT;
    const int bn   = blockIdx.x * NT;
    const int z    = blockIdx.z;
    const bool do_lo = (lo_mask >> z) & 1u;

    const __half* Bh = (z == 0) ? B0h : (z == 1) ? B1h : B2h;
    __half* Ch = (z == 0) ? C0h : (z == 1) ? C1h : C2h;
    __half* Cl = (z == 0) ? C0l : (z == 1) ? C1l : C2l;
    const float scale = (z == 0) ? scale0 : 1.0f;

    const int wm0 = (wid & 1) * 32;
    const int wn0 = (wid >> 1) * 32;

    const char* gah = (const char*)Ah + (size_t)bm * (HIDDEN * 2);
    const char* gal = (const char*)Al + (size_t)bm * (HIDDEN * 2);
    const char* gbh = (const char*)Bh + (size_t)bn * (HIDDEN * 2);

    const int a_r = lane & 15;
    const uint32_t a_k16 = (lane >> 4) * 16;
    uint32_t a_rb[2], a_xm[2];
    #pragma unroll
    for (int i = 0; i < 2; i++) {
        int row = wm0 + i * 16 + a_r;
        a_rb[i] = (uint32_t)row * 128;
        a_xm[i] = (uint32_t)(row & 7) * 16;
    }
    const int b_r = ((lane >> 4) & 1) * 8 + (lane & 7);
    const uint32_t b_k16 = ((lane >> 3) & 1) * 16;
    uint32_t b_rb[2], b_xm[2];
    #pragma unroll
    for (int j = 0; j < 2; j++) {
        int row = wn0 + j * 16 + b_r;
        b_rb[j] = (uint32_t)row * 128;
        b_xm[j] = (uint32_t)(row & 7) * 16;
    }

    float acc[2][4][4] = {};

    auto load_stage = [&](int s, int c) {
        const uint32_t st = sb + (uint32_t)s * STG2;
        const size_t cb = (size_t)c * 128;
        #pragma unroll
        for (int u = 0; u < 2; u++) {
            int idx = u * 256 + tid;
            uint32_t bo = (uint32_t)idx << 4;
            uint32_t sw = bo ^ ((bo >> 3) & 0x70);
            size_t go = (size_t)(idx >> 3) * (HIDDEN * 2) + (size_t)(idx & 7) * 16 + cb;
            cp16(st + sw, gah + go);
            if (do_lo) cp16(st + ST_A + sw, gal + go);
        }
        #pragma unroll
        for (int u = 0; u < 4; u++) {
            int idx = u * 256 + tid;
            uint32_t bo = (uint32_t)idx << 4;
            uint32_t sw = bo ^ ((bo >> 3) & 0x70);
            size_t go = (size_t)(idx >> 3) * (HIDDEN * 2) + (size_t)(idx & 7) * 16 + cb;
            cp16(st + 2 * ST_A + sw, gbh + go);
        }
        CP_COMMIT();
    };

    load_stage(0, 0);

    for (int c = 0; c < NCHUNK; c++) {
        CP_WAIT(0);
        __syncthreads();
        if (c + 1 < NCHUNK) load_stage((c + 1) & 1, c + 1);

        const uint32_t st  = sb + (uint32_t)(c & 1) * STG2;
        const uint32_t tAh = st;
        const uint32_t tAl = st + ST_A;
        const uint32_t tBh = st + 2 * ST_A;

        #pragma unroll
        for (int ks = 0; ks < 4; ks++) {
            const uint32_t ak = (uint32_t)ks * 32 + a_k16;
            const uint32_t bk = (uint32_t)ks * 32 + b_k16;

            uint32_t ah[2][4], al[2][4], bh[2][4];
            #pragma unroll
            for (int i = 0; i < 2; i++) {
                uint32_t off = a_rb[i] + (ak ^ a_xm[i]);
                ldsm_x4(ah[i][0], ah[i][1], ah[i][2], ah[i][3], tAh + off);
                if (do_lo)
                    ldsm_x4(al[i][0], al[i][1], al[i][2], al[i][3], tAl + off);
            }
            #pragma unroll
            for (int j = 0; j < 2; j++) {
                uint32_t off = b_rb[j] + (bk ^ b_xm[j]);
                ldsm_x4(bh[j][0], bh[j][1], bh[j][2], bh[j][3], tBh + off);
            }
            #pragma unroll
            for (int i = 0; i < 2; i++)
                #pragma unroll
                for (int j = 0; j < 4; j++)
                    mma_f16(acc[i][j], ah[i],
                            bh[j >> 1][(j & 1) * 2], bh[j >> 1][(j & 1) * 2 + 1]);
            if (do_lo) {
                #pragma unroll
                for (int i = 0; i < 2; i++)
                    #pragma unroll
                    for (int j = 0; j < 4; j++)
                        mma_f16(acc[i][j], al[i],
                                bh[j >> 1][(j & 1) * 2], bh[j >> 1][(j & 1) * 2 + 1]);
            }
        }
    }

    const int cr = lane >> 2;
    const int cc = (lane & 3) * 2;
    #pragma unroll
    for (int i = 0; i < 2; i++) {
        #pragma unroll
        for (int j = 0; j < 4; j++) {
            int row = bm + wm0 + i * 16 + cr;
            int col = bn + wn0 + j * 8 + cc;
            if (Cf) {
                *(float2*)(Cf + (size_t)row * HIDDEN + col) =
                    make_float2(acc[i][j][0], acc[i][j][1]);
                *(float2*)(Cf + (size_t)(row + 8) * HIDDEN + col) =
                    make_float2(acc[i][j][2], acc[i][j][3]);
            } else if (Cl) {
                uint32_t h0, l0, h1, l1;
                split2h(acc[i][j][0] * scale, acc[i][j][1] * scale, h0, l0);
                split2h(acc[i][j][2] * scale, acc[i][j][3] * scale, h1, l1);
                *(uint32_t*)(Ch + (size_t)row * HIDDEN + col)       = h0;
                *(uint32_t*)(Cl + (size_t)row * HIDDEN + col)       = l0;
                *(uint32_t*)(Ch + (size_t)(row + 8) * HIDDEN + col) = h1;
                *(uint32_t*)(Cl + (size_t)(row + 8) * HIDDEN + col) = l1;
            } else {
                *(uint32_t*)(Ch + (size_t)row * HIDDEN + col) =
                    pack2h(acc[i][j][0] * scale, acc[i][j][1] * scale);
                *(uint32_t*)(Ch + (size_t)(row + 8) * HIDDEN + col) =
                    pack2h(acc[i][j][2] * scale, acc[i][j][3] * scale);
            }
        }
    }
}

// ---------------- flash attention, fp16 (base-2 softmax) ------------------------
// QK: qh*kh + qh*kl (2-pass). PV: p*vh (single pass). Output: plain fp16.
__global__ __launch_bounds__(256)
void attn_mma(const __half* __restrict__ Qh,
              const __half* __restrict__ Kh, const __half* __restrict__ Kl,
              const __half* __restrict__ Vh,
              __half* __restrict__ AOh)
{
    extern __shared__ __align__(1024) char smem[];
    const uint32_t sb = smem_u32(smem);
    const int tid  = threadIdx.x;
    const int wid  = tid >> 5;
    const int lane = tid & 31;
    const int q0   = blockIdx.x * 128;
    const int h    = blockIdx.y;
    const int b    = blockIdx.z;

    const size_t hb = ((size_t)b * SEQ) * HIDDEN + (size_t)h * DK;
    const char* gqh = (const char*)(Qh + hb + (size_t)q0 * HIDDEN);
    const char* gkh = (const char*)(Kh + hb);
    const char* gkl = (const char*)(Kl + hb);
    const char* gvh = (const char*)(Vh + hb);

    auto load_tile = [&](uint32_t soff, const char* g) {
        #pragma unroll
        for (int r = 0; r < 8; r++) {
            int idx = r * 256 + tid;
            int row = idx >> 4, u = idx & 15;
            uint32_t sa = sb + soff + (uint32_t)(u >> 3) * 16384
                        + (uint32_t)row * 128
                        + (((uint32_t)(u & 7) * 16) ^ ((uint32_t)(row & 7) * 16));
            cp16(sa, g + (size_t)row * (HIDDEN * 2) + (size_t)u * 16);
        }
    };

    load_tile(A_SQH, gqh);
    load_tile(A_SKH, gkh);
    load_tile(A_SKL, gkl);
    CP_COMMIT();
    CP_WAIT(0);
    __syncthreads();

    float of[16][4] = {};
    float m0 = -INFINITY, m1 = -INFINITY, l0 = 0.f, l1 = 0.f;

    const uint32_t q_row = (uint32_t)(16 * wid + (lane & 15));
    const uint32_t q_kof = (uint32_t)(lane >> 4) * 16;
    const uint32_t q_xm  = (q_row & 7) * 16;
    const uint32_t q_rb  = q_row * 128;

    const uint32_t k_r   = (uint32_t)(((lane >> 4) & 1) * 8 + (lane & 7));
    const uint32_t k_kof = (uint32_t)((lane >> 3) & 1) * 16;

    const int v_grp  = lane >> 3;
    const uint32_t v_krow = (uint32_t)((v_grp & 1) * 8 + (lane & 7));
    const uint32_t v_ncol = (uint32_t)((v_grp >> 1) * 8);

    for (int t = 0; t < 16; t++) {
        load_tile(A_SVH, gvh + (size_t)t * 128 * (HIDDEN * 2));
        CP_COMMIT();

        float sf[16][4] = {};
        #pragma unroll
        for (int ks = 0; ks < 8; ks++) {
            uint32_t qa = sb + A_SQH + (uint32_t)(ks >> 2) * 16384 + q_rb
                        + ((((uint32_t)(ks & 3) * 32) + q_kof) ^ q_xm);
            uint32_t qh4[4];
            ldsm_x4(qh4[0], qh4[1], qh4[2], qh4[3], qa);
            #pragma unroll
            for (int j16 = 0; j16 < 8; j16++) {
                uint32_t krow = (uint32_t)j16 * 16 + k_r;
                uint32_t ka = sb + A_SKH + (uint32_t)(ks >> 2) * 16384 + krow * 128
                            + ((((uint32_t)(ks & 3) * 32) + k_kof) ^ ((krow & 7) * 16));
                uint32_t kh4[4], kl4[4];
                ldsm_x4(kh4[0], kh4[1], kh4[2], kh4[3], ka);
                ldsm_x4(kl4[0], kl4[1], kl4[2], kl4[3], ka + (A_SKL - A_SKH));
                mma_f16(sf[2*j16],   qh4, kh4[0], kh4[1]);
                mma_f16(sf[2*j16+1], qh4, kh4[2], kh4[3]);
                mma_f16(sf[2*j16],   qh4, kl4[0], kl4[1]);
                mma_f16(sf[2*j16+1], qh4, kl4[2], kl4[3]);
            }
        }

        CP_WAIT(0);
        __syncthreads();

        if (t + 1 < 16) {
            load_tile(A_SKH, gkh + (size_t)(t + 1) * 128 * (HIDDEN * 2));
            load_tile(A_SKL, gkl + (size_t)(t + 1) * 128 * (HIDDEN * 2));
            CP_COMMIT();
        }

        // ---- online softmax, base 2 ----
        float tm0 = m0, tm1 = m1;
        #pragma unroll
        for (int f = 0; f < 16; f++) {
            tm0 = fmaxf(tm0, fmaxf(sf[f][0], sf[f][1]));
            tm1 = fmaxf(tm1, fmaxf(sf[f][2], sf[f][3]));
        }
        tm0 = fmaxf(tm0, __shfl_xor_sync(0xffffffff, tm0, 1));
        tm0 = fmaxf(tm0, __shfl_xor_sync(0xffffffff, tm0, 2));
        tm1 = fmaxf(tm1, __shfl_xor_sync(0xffffffff, tm1, 1));
        tm1 = fmaxf(tm1, __shfl_xor_sync(0xffffffff, tm1, 2));
        float cor0 = exp2f(m0 - tm0);
        float cor1 = exp2f(m1 - tm1);
        m0 = tm0; m1 = tm1;
        float s0 = 0.f, s1 = 0.f;
        #pragma unroll
        for (int f = 0; f < 16; f++) {
            sf[f][0] = exp2f(sf[f][0] - m0);
            sf[f][1] = exp2f(sf[f][1] - m0);
            sf[f][2] = exp2f(sf[f][2] - m1);
            sf[f][3] = exp2f(sf[f][3] - m1);
            s0 += sf[f][0] + sf[f][1];
            s1 += sf[f][2] + sf[f][3];
        }
        s0 += __shfl_xor_sync(0xffffffff, s0, 1);
        s0 += __shfl_xor_sync(0xffffffff, s0, 2);
        s1 += __shfl_xor_sync(0xffffffff, s1, 1);
        s1 += __shfl_xor_sync(0xffffffff, s1, 2);
        l0 = l0 * cor0 + s0;
        l1 = l1 * cor1 + s1;
        #pragma unroll
        for (int f = 0; f < 16; f++) {
            of[f][0] *= cor0; of[f][1] *= cor0;
            of[f][2] *= cor1; of[f][3] *= cor1;
        }

        // ---- O += P Vh (single pass) ----
        #pragma unroll
        for (int ks = 0; ks < 8; ks++) {
            uint32_t ph[4];
            ph[0] = pack2h(sf[2*ks][0],   sf[2*ks][1]);
            ph[1] = pack2h(sf[2*ks][2],   sf[2*ks][3]);
            ph[2] = pack2h(sf[2*ks+1][0], sf[2*ks+1][1]);
            ph[3] = pack2h(sf[2*ks+1][2], sf[2*ks+1][3]);
            uint32_t vkey = (uint32_t)ks * 16 + v_krow;
            #pragma unroll
            for (int j16 = 0; j16 < 8; j16++) {
                uint32_t ncol = (uint32_t)j16 * 16 + v_ncol;
                uint32_t va = sb + A_SVH + (ncol >> 6) * 16384 + vkey * 128
                            + (((ncol & 63) * 2) ^ ((vkey & 7) * 16));
                uint32_t vh4[4];
                ldsm_x4_t(vh4[0], vh4[1], vh4[2], vh4[3], va);
                mma_f16(of[2*j16],   ph, vh4[0], vh4[1]);
                mma_f16(of[2*j16+1], ph, vh4[2], vh4[3]);
            }
        }

        CP_WAIT(0);
        __syncthreads();
    }

    const float inv0 = 1.f / l0;
    const float inv1 = 1.f / l1;
    const int r0 = q0 + 16 * wid + (lane >> 2);
    const int cc = (lane & 3) * 2;
    #pragma unroll
    for (int f = 0; f < 16; f++) {
        int col = f * 8 + cc;
        size_t o0 = hb + (size_t)r0 * HIDDEN + col;
        size_t o1 = hb + (size_t)(r0 + 8) * HIDDEN + col;
        *(uint32_t*)(AOh + o0) = pack2h(of[f][0] * inv0, of[f][1] * inv0);
        *(uint32_t*)(AOh + o1) = pack2h(of[f][2] * inv1, of[f][3] * inv1);
    }
}

// ------------------------------------------------------------------------------
extern "C" void kernel_launch(void* const* d_in, const int* in_sizes, int n_in,
                              void* d_out, int out_size)
{
    const float* x  = (const float*)d_in[0];
    const float* wq = (const float*)d_in[1];
    const float* wk = (const float*)d_in[2];
    const float* wv = (const float*)d_in[3];
    const float* wo = (const float*)d_in[4];
    float* out = (float*)d_out;

    __half *qh, *ql, *kh, *kl, *vh, *vl, *xh, *xl, *aoh;
    __half *wqh, *wkh, *wvh, *woh, *wol;
    cudaGetSymbolAddress((void**)&qh,  g_qh);  cudaGetSymbolAddress((void**)&ql,  g_ql);
    cudaGetSymbolAddress((void**)&kh,  g_kh);  cudaGetSymbolAddress((void**)&kl,  g_kl);
    cudaGetSymbolAddress((void**)&vh,  g_vh);  cudaGetSymbolAddress((void**)&vl,  g_vl);
    cudaGetSymbolAddress((void**)&xh,  g_xh);  cudaGetSymbolAddress((void**)&xl,  g_xl);
    cudaGetSymbolAddress((void**)&aoh, g_aoh);
    cudaGetSymbolAddress((void**)&wqh, g_wqh);
    cudaGetSymbolAddress((void**)&wkh, g_wkh);
    cudaGetSymbolAddress((void**)&wvh, g_wvh);
    cudaGetSymbolAddress((void**)&woh, g_woh);
    cudaGetSymbolAddress((void**)&wol, g_wol);

    cudaFuncSetAttribute(gemm_f16, cudaFuncAttributeMaxDynamicSharedMemorySize,
                         SMEM_G2);
    cudaFuncSetAttribute(attn_mma, cudaFuncAttributeMaxDynamicSharedMemorySize,
                         SMEM_ATTN);

    // fused convert: all 5 tensors -> fp16 hi/lo (w lo halves parked in q/k/v lo
    // scratch, consumed only before the projections overwrite them; wo_lo unused)
    dim3 gcvt((HIDDEN * HIDDEN) / 4 / 256, 5);   // (16384, 5)
    cvt5<<<gcvt, 256>>>(
        (const float4*)x,  (uint32_t*)xh,  (uint32_t*)xl,
        (const float4*)wq, (uint32_t*)wqh, (uint32_t*)ql,
        (const float4*)wk, (uint32_t*)wkh, (uint32_t*)kl,
        (const float4*)wv, (uint32_t*)wvh, (uint32_t*)vl,
        (const float4*)wo, (uint32_t*)woh, (uint32_t*)wol);

    // fused Q/K/V projections: Q,K 2-pass (lo_mask bits 0,1), V single-pass.
    // Q/K outputs hi/lo (K's lo feeds the 2-pass QK); V and Q lo: Q needs hi only
    // -> still write Q hi/lo (cheap) to keep one epilogue shape; V writes plain fp16.
    dim3 gqkv(HIDDEN / NT, MTOK / MT, 3);   // (32, 64, 3)
    gemm_f16<<<gqkv, 256, SMEM_G2>>>(
        xh, xl, wqh, wkh, wvh,
        qh, ql, kh, kl, vh, nullptr,   // V: plain fp16 (no lo output)
        nullptr, QSCALE2, 0x3u);

    dim3 ga(SEQ / 128, NHEADS, BATCH);      // (16, 32, 2)
    attn_mma<<<ga, 256, SMEM_ATTN>>>(qh, kh, kl, vh, aoh);

    // output projection: single-pass fp16, fp32 result
    dim3 go(HIDDEN / NT, MTOK / MT, 1);     // (32, 64, 1)
    gemm_f16<<<go, 256, SMEM_G2>>>(
        aoh, aoh, woh, woh, woh,
        nullptr, nullptr, nullptr, nullptr, nullptr, nullptr, out, 1.0f, 0x0u);
}